// round 2
// baseline (speedup 1.0000x reference)
#include <cuda_runtime.h>
#include <math.h>

typedef unsigned long long ull;

#define T_SEQ 128
#define BATCH 64
#define EMB   2048
#define HID   2048
#define VOCAB 10000
#define MB_   (T_SEQ * BATCH)   /* 8192 */

/* ------------------------------------------------------------------ */
/* Scratch (device globals only — no runtime allocation)               */
/* ------------------------------------------------------------------ */
__device__ float g_X0[(size_t)MB_ * HID];   /* precomputed emb@W0x^T + b0  (64MB) */
__device__ float g_H [(size_t)MB_ * HID];   /* layer-1 hidden per step     (64MB) */
__device__ float g_h0[2][BATCH * HID];      /* layer-0 hidden ping-pong           */
__device__ int   g_is64;                    /* index dtype flag (set per launch)  */

/* ------------------------------------------------------------------ */
/* Packed f32x2 helpers (full-rate FMA pipe on sm_103a)                */
/* ------------------------------------------------------------------ */
__device__ __forceinline__ ull pk2(float x, float y) {
    ull r; asm("mov.b64 %0, {%1,%2};" : "=l"(r) : "f"(x), "f"(y)); return r;
}
__device__ __forceinline__ float2 upk2(ull v) {
    float2 r; asm("mov.b64 {%0,%1}, %2;" : "=f"(r.x), "=f"(r.y) : "l"(v)); return r;
}
#define FMA2(acc, a, b) asm("fma.rn.f32x2 %0, %1, %2, %0;" : "+l"(acc) : "l"(a), "l"(b))

/* ------------------------------------------------------------------ */
/* Detect whether the index input is int64 or int32.                   */
/* int64 (values < 10000) => every odd 32-bit word of the first 16     */
/* pairs is zero. For int32 random indices that is ~impossible.        */
/* Reads only the first 128 bytes (safe under both layouts).           */
/* ------------------------------------------------------------------ */
__global__ void detect_idx_kernel(const unsigned int* __restrict__ p) {
    if (threadIdx.x == 0) {
        unsigned int o = 0;
#pragma unroll
        for (int i = 0; i < 16; i++) o |= p[2 * i + 1];
        g_is64 = (o == 0u) ? 1 : 0;
    }
}

/* ------------------------------------------------------------------ */
/* Big NT GEMM:  C[M,N] = A[M,K] * B[N,K]^T + bias                     */
/* A rows optionally gathered through an index array (embedding fuse). */
/* BM=64, BN=64, BK=16, 256 threads, 4x4 micro-tile, f32x2 FMAs.       */
/* M and K are multiples of 64/16 for all call sites; N is guarded.    */
/* ------------------------------------------------------------------ */
__global__ __launch_bounds__(256) void gemm_nt(
    const float* __restrict__ A, const void* __restrict__ aidx, int lda,
    const float* __restrict__ B, int ldb, const float* __restrict__ bias,
    float* __restrict__ C, int ldc, int N, int K)
{
    __shared__ float As[16][68];   /* k-major, m contiguous, 16B-aligned rows */
    __shared__ float Bs[16][68];

    const int tid = threadIdx.x;
    const int bm  = blockIdx.y * 64;
    const int bn  = blockIdx.x * 64;

    /* loader mapping: one float4 along K per thread */
    const int lr = tid >> 2;          /* tile row 0..63      */
    const int lk = (tid & 3) * 4;     /* k offset 0,4,8,12   */

    const float* arow;
    {
        size_t r;
        const int m = bm + lr;
        if (aidx) {
            if (g_is64) r = (size_t)((const long long*)aidx)[m];
            else        r = (size_t)((const int*)aidx)[m];
        } else {
            r = (size_t)m;
        }
        arow = A + r * (size_t)lda;
    }
    const int  nrow = bn + lr;
    const bool bok  = (nrow < N);
    const float* brow = B + (size_t)(bok ? nrow : 0) * (size_t)ldb;

    /* compute mapping: 16 n-groups x 16 m-groups */
    const int tx = tid & 15;          /* n-group */
    const int ty = tid >> 4;          /* m-group */
    const int n0 = tx * 4;
    const int m0 = ty * 4;

    ull acc[4][2] = {{0ull,0ull},{0ull,0ull},{0ull,0ull},{0ull,0ull}};

    for (int k0 = 0; k0 < K; k0 += 16) {
        float4 av = *(const float4*)(arow + k0 + lk);
        float4 bv = bok ? *(const float4*)(brow + k0 + lk)
                        : make_float4(0.f, 0.f, 0.f, 0.f);
        __syncthreads();
        As[lk+0][lr] = av.x; As[lk+1][lr] = av.y; As[lk+2][lr] = av.z; As[lk+3][lr] = av.w;
        Bs[lk+0][lr] = bv.x; Bs[lk+1][lr] = bv.y; Bs[lk+2][lr] = bv.z; Bs[lk+3][lr] = bv.w;
        __syncthreads();
#pragma unroll
        for (int k = 0; k < 16; k++) {
            union { float4 f; ull u[2]; } b4;
            b4.f = *(const float4*)&Bs[k][n0];
            float4 a4 = *(const float4*)&As[k][m0];
            ull aa;
            aa = pk2(a4.x, a4.x); FMA2(acc[0][0], aa, b4.u[0]); FMA2(acc[0][1], aa, b4.u[1]);
            aa = pk2(a4.y, a4.y); FMA2(acc[1][0], aa, b4.u[0]); FMA2(acc[1][1], aa, b4.u[1]);
            aa = pk2(a4.z, a4.z); FMA2(acc[2][0], aa, b4.u[0]); FMA2(acc[2][1], aa, b4.u[1]);
            aa = pk2(a4.w, a4.w); FMA2(acc[3][0], aa, b4.u[0]); FMA2(acc[3][1], aa, b4.u[1]);
        }
    }

#pragma unroll
    for (int i = 0; i < 4; i++) {
        float2 p0 = upk2(acc[i][0]);
        float2 p1 = upk2(acc[i][1]);
        float vals[4] = { p0.x, p0.y, p1.x, p1.y };
        const int m = bm + m0 + i;
#pragma unroll
        for (int j = 0; j < 4; j++) {
            const int n = bn + n0 + j;
            if (n < N)
                C[(size_t)m * ldc + n] = vals[j] + (bias ? bias[n] : 0.f);
        }
    }
}

/* ------------------------------------------------------------------ */
/* Recurrent step GEMM:                                                */
/*   C[64,2048] = tanh( A1@W1p^T (+ A2@W2p^T) (+ Xadd) (+ bias) )      */
/* W rows indexed as Wp[n*4096 + k] (column-offset folded into Wp).    */
/* BM=64 (=M), BN=16, BK=32, 128 threads, 8m x 1n micro-tile.          */
/* ------------------------------------------------------------------ */
__global__ __launch_bounds__(128) void rnn_step(
    const float* __restrict__ A1, const float* __restrict__ A2,
    const float* __restrict__ W1p, const float* __restrict__ W2p,
    const float* __restrict__ Xadd, const float* __restrict__ bias,
    float* __restrict__ C)
{
    __shared__ float As[32][68];   /* k-major, m contiguous */
    __shared__ float Bs[32][20];   /* k-major, n contiguous */

    const int tid = threadIdx.x;
    const int bn  = blockIdx.x * 16;

    /* A loader: thread covers k range [ah, ah+16) of its row */
    const int ar = tid >> 1;          /* 0..63 */
    const int ah = (tid & 1) * 16;
    /* B loader: one float4 per thread */
    const int br = tid >> 3;          /* 0..15 */
    const int bv = (tid & 7) * 4;

    const int tx = tid & 15;          /* n column   */
    const int ty = tid >> 4;          /* 0..7       */
    const int m0 = ty * 8;

    ull acc[4] = {0ull, 0ull, 0ull, 0ull};  /* 8 m-outputs as 4 pairs */

    for (int phase = 0; phase < 2; phase++) {
        const float* A  = phase ? A2  : A1;
        const float* Wp = phase ? W2p : W1p;
        if (A == 0) break;
        const float* arow = A  + (size_t)ar * HID;
        const float* brow = Wp + (size_t)(bn + br) * (size_t)(EMB + HID);

        for (int k0 = 0; k0 < HID; k0 += 32) {
            float4 av[4];
#pragma unroll
            for (int v = 0; v < 4; v++)
                av[v] = *(const float4*)(arow + k0 + ah + v * 4);
            float4 bvv = *(const float4*)(brow + k0 + bv);
            __syncthreads();
#pragma unroll
            for (int v = 0; v < 4; v++) {
                const int kk = ah + v * 4;
                As[kk+0][ar] = av[v].x; As[kk+1][ar] = av[v].y;
                As[kk+2][ar] = av[v].z; As[kk+3][ar] = av[v].w;
            }
            Bs[bv+0][br] = bvv.x; Bs[bv+1][br] = bvv.y;
            Bs[bv+2][br] = bvv.z; Bs[bv+3][br] = bvv.w;
            __syncthreads();
#pragma unroll
            for (int k = 0; k < 32; k++) {
                const float b = Bs[k][tx];
                const ull  bb = pk2(b, b);
                union { float4 f; ull u[2]; } a0, a1;
                a0.f = *(const float4*)&As[k][m0];
                a1.f = *(const float4*)&As[k][m0 + 4];
                FMA2(acc[0], a0.u[0], bb);
                FMA2(acc[1], a0.u[1], bb);
                FMA2(acc[2], a1.u[0], bb);
                FMA2(acc[3], a1.u[1], bb);
            }
        }
    }

    const float badd = bias ? bias[bn + tx] : 0.f;
#pragma unroll
    for (int i = 0; i < 4; i++) {
        float2 v = upk2(acc[i]);
        const int ma = m0 + 2 * i;
        const int mb = ma + 1;
        const float xa = Xadd ? Xadd[(size_t)ma * HID + bn + tx] : 0.f;
        const float xb = Xadd ? Xadd[(size_t)mb * HID + bn + tx] : 0.f;
        C[(size_t)ma * HID + bn + tx] = tanhf(v.x + badd + xa);
        C[(size_t)mb * HID + bn + tx] = tanhf(v.y + badd + xb);
    }
}

/* ------------------------------------------------------------------ */
/* Pack final hidden state behind the logits in d_out                  */
/* ------------------------------------------------------------------ */
__global__ void copy_final(const float4* __restrict__ h0,
                           const float4* __restrict__ h1,
                           float4* __restrict__ out)
{
    const int i = blockIdx.x * blockDim.x + threadIdx.x;
    if (i < (BATCH * HID) / 4)            out[i] = h0[i];
    else if (i < (2 * BATCH * HID) / 4)   out[i] = h1[i - (BATCH * HID) / 4];
}

/* ------------------------------------------------------------------ */
extern "C" void kernel_launch(void* const* d_in, const int* in_sizes, int n_in,
                              void* d_out, int out_size)
{
    (void)in_sizes; (void)n_in; (void)out_size;

    const void*  inputs = d_in[0];                       /* [128,64] int64 or int32 */
    const float* hidden = (const float*)d_in[1];         /* [2,64,2048]  */
    const float* emb    = (const float*)d_in[2];         /* [10000,2048] */
    const float* W0     = (const float*)d_in[3];         /* [2048,4096]  */
    const float* b0     = (const float*)d_in[4];
    const float* W1     = (const float*)d_in[5];         /* [2048,4096]  */
    const float* b1     = (const float*)d_in[6];
    const float* Wout   = (const float*)d_in[7];         /* [10000,2048] */
    const float* bout   = (const float*)d_in[8];
    float* out = (float*)d_out;

    float *pX0, *pH, *ph0;
    cudaGetSymbolAddress((void**)&pX0, g_X0);
    cudaGetSymbolAddress((void**)&pH,  g_H);
    cudaGetSymbolAddress((void**)&ph0, g_h0);

    /* index dtype sniff (device-side, per launch, deterministic) */
    detect_idx_kernel<<<1, 32>>>((const unsigned int*)inputs);

    /* X0 = emb_table[inputs] @ W0x^T + b0   (embedding gather fused) */
    {
        dim3 g(HID / 64, MB_ / 64);   /* 32 x 128 */
        gemm_nt<<<g, 256>>>(emb, inputs, EMB,
                            W0, EMB + HID, b0,
                            pX0, HID, HID, EMB);
    }

    /* sequential scan: 128 steps x 2 dependent skinny GEMMs */
    for (int t = 0; t < T_SEQ; t++) {
        const float* h0src = t ? (ph0 + ((t - 1) & 1) * (BATCH * HID)) : hidden;
        float*       h0dst = ph0 + (t & 1) * (BATCH * HID);
        /* layer 0: tanh(X0[t] + h0 @ W0h^T)   (b0 folded into X0) */
        rnn_step<<<HID / 16, 128>>>(h0src, (const float*)0,
                                    W0 + EMB, (const float*)0,
                                    pX0 + (size_t)t * BATCH * HID, (const float*)0,
                                    h0dst);
        /* layer 1: tanh(h0' @ W1x^T + h1 @ W1h^T + b1) */
        const float* h1src = t ? (pH + (size_t)(t - 1) * BATCH * HID)
                               : (hidden + BATCH * HID);
        rnn_step<<<HID / 16, 128>>>(h0dst, h1src,
                                    W1, W1 + HID,
                                    (const float*)0, b1,
                                    pH + (size_t)t * BATCH * HID);
    }

    /* logits = H @ Wout^T + bout  -> d_out[0 : 8192*10000] */
    {
        dim3 g((VOCAB + 63) / 64, MB_ / 64);   /* 157 x 128 */
        gemm_nt<<<g, 256>>>(pH, (const void*)0, HID,
                            Wout, HID, bout,
                            out, VOCAB, VOCAB, HID);
    }

    /* final_hidden -> d_out[8192*10000 : +2*64*2048] */
    copy_final<<<256, 256>>>(
        (const float4*)(ph0 + ((T_SEQ - 1) & 1) * (BATCH * HID)),
        (const float4*)(pH + (size_t)(T_SEQ - 1) * BATCH * HID),
        (float4*)(out + (size_t)MB_ * VOCAB));
}

// round 5
// speedup vs baseline: 1.9371x; 1.9371x over previous
#include <cuda_runtime.h>
#include <math.h>

typedef unsigned long long ull;

#define T_SEQ 128
#define BATCH 64
#define EMB   2048
#define HID   2048
#define VOCAB 10000
#define MB_   (T_SEQ * BATCH)   /* 8192 */

/* ------------------------------------------------------------------ */
/* Scratch (device globals only — no runtime allocation)               */
/* ------------------------------------------------------------------ */
__device__ float g_X0[(size_t)MB_ * HID];    /* emb@W0x^T + b0  (64MB)      */
__device__ float g_H [(size_t)MB_ * HID];    /* layer-1 hidden per step     */
__device__ float g_h0[2][BATCH * HID];       /* layer-0 hidden ping-pong    */
__device__ float g_part[8][BATCH * HID];     /* split-K partials (4MB)      */
__device__ int   g_is64;

/* ------------------------------------------------------------------ */
/* Packed f32x2 helpers                                                */
/* ------------------------------------------------------------------ */
__device__ __forceinline__ ull pk2(float x, float y) {
    ull r; asm("mov.b64 %0, {%1,%2};" : "=l"(r) : "f"(x), "f"(y)); return r;
}
__device__ __forceinline__ float2 upk2(ull v) {
    float2 r; asm("mov.b64 {%0,%1}, %2;" : "=f"(r.x), "=f"(r.y) : "l"(v)); return r;
}
#define FMA2(acc, a, b) asm("fma.rn.f32x2 %0, %1, %2, %0;" : "+l"(acc) : "l"(a), "l"(b))

/* ------------------------------------------------------------------ */
__global__ void detect_idx_kernel(const unsigned int* __restrict__ p) {
    if (threadIdx.x == 0) {
        unsigned int o = 0;
#pragma unroll
        for (int i = 0; i < 16; i++) o |= p[2 * i + 1];
        g_is64 = (o == 0u) ? 1 : 0;
    }
}

/* ------------------------------------------------------------------ */
/* Big NT GEMM: C[M,N] = A[M,K] * B[N,K]^T + bias                      */
/* 128x128 tile, BK=16, 256 threads, 8x8 micro-tile, f32x2 FMAs.       */
/* As holds duplicated (a,a) pairs so no packing in the inner loop.    */
/* ------------------------------------------------------------------ */
__global__ __launch_bounds__(256) void gemm_big(
    const float* __restrict__ A, const void* __restrict__ aidx, int lda,
    const float* __restrict__ B, int ldb, const float* __restrict__ bias,
    float* __restrict__ C, int ldc, int N, int K)
{
    __shared__ __align__(16) ull   As [16][130];   /* dup pairs, k-major */
    __shared__ __align__(16) float Bsf[16][132];

    const int tid = threadIdx.x;
    const int bm  = blockIdx.y * 128;
    const int bn  = blockIdx.x * 128;

    /* loaders: row = tid>>1 (0..127), k-half = (tid&1)*8 */
    const int lr = tid >> 1;
    const int lk = (tid & 1) * 8;

    const float* arow;
    {
        size_t r;
        const int m = bm + lr;
        if (aidx) {
            if (g_is64) r = (size_t)((const long long*)aidx)[m];
            else        r = (size_t)((const int*)aidx)[m];
        } else r = (size_t)m;
        arow = A + r * (size_t)lda;
    }
    const int  nrow = bn + lr;
    const bool bok  = (nrow < N);
    const float* brow = B + (size_t)(bok ? nrow : 0) * (size_t)ldb;

    const int tx = tid & 15;      /* n-group */
    const int ty = tid >> 4;      /* m-group */
    const int n0 = tx * 8;
    const int m0 = ty * 8;

    ull acc[8][4];
#pragma unroll
    for (int i = 0; i < 8; i++)
#pragma unroll
        for (int j = 0; j < 4; j++) acc[i][j] = 0ull;

    for (int k0 = 0; k0 < K; k0 += 16) {
        float4 a0 = *(const float4*)(arow + k0 + lk);
        float4 a1 = *(const float4*)(arow + k0 + lk + 4);
        float4 b0 = bok ? *(const float4*)(brow + k0 + lk)
                        : make_float4(0.f,0.f,0.f,0.f);
        float4 b1 = bok ? *(const float4*)(brow + k0 + lk + 4)
                        : make_float4(0.f,0.f,0.f,0.f);
        __syncthreads();
        As[lk+0][lr] = pk2(a0.x, a0.x);  As[lk+1][lr] = pk2(a0.y, a0.y);
        As[lk+2][lr] = pk2(a0.z, a0.z);  As[lk+3][lr] = pk2(a0.w, a0.w);
        As[lk+4][lr] = pk2(a1.x, a1.x);  As[lk+5][lr] = pk2(a1.y, a1.y);
        As[lk+6][lr] = pk2(a1.z, a1.z);  As[lk+7][lr] = pk2(a1.w, a1.w);
        Bsf[lk+0][lr] = b0.x;  Bsf[lk+1][lr] = b0.y;
        Bsf[lk+2][lr] = b0.z;  Bsf[lk+3][lr] = b0.w;
        Bsf[lk+4][lr] = b1.x;  Bsf[lk+5][lr] = b1.y;
        Bsf[lk+6][lr] = b1.z;  Bsf[lk+7][lr] = b1.w;
        __syncthreads();
#pragma unroll
        for (int k = 0; k < 16; k++) {
            ull b[4];
            {
                longlong2 t0 = *(const longlong2*)&Bsf[k][n0];
                longlong2 t1 = *(const longlong2*)&Bsf[k][n0 + 4];
                b[0] = (ull)t0.x; b[1] = (ull)t0.y;
                b[2] = (ull)t1.x; b[3] = (ull)t1.y;
            }
            ull a[8];
#pragma unroll
            for (int i = 0; i < 4; i++) {
                longlong2 t = *(const longlong2*)&As[k][m0 + 2*i];
                a[2*i] = (ull)t.x; a[2*i+1] = (ull)t.y;
            }
#pragma unroll
            for (int mi = 0; mi < 8; mi++)
#pragma unroll
                for (int nj = 0; nj < 4; nj++)
                    FMA2(acc[mi][nj], a[mi], b[nj]);
        }
    }

#pragma unroll
    for (int mi = 0; mi < 8; mi++) {
        const size_t m = (size_t)(bm + m0 + mi);
#pragma unroll
        for (int nj = 0; nj < 4; nj++) {
            const int n = bn + n0 + 2*nj;
            if (n < N) {
                float2 v = upk2(acc[mi][nj]);
                v.x += bias[n]; v.y += bias[n+1];   /* N even, so n<N => n+1<N */
                *(float2*)(C + m * (size_t)ldc + n) = v;
            }
        }
    }
}

/* ------------------------------------------------------------------ */
/* Recurrent step partial GEMM (split-K across blocks):                */
/*   part[kg][64][2048] = A[64, chunk] @ W[64rows? no: n rows]^T       */
/* grid = (2048/64 = 32, KG=8).  kg < kgHalf -> (A1, W1); else (A2,W2) */
/* BM=64, BN=64, BK=16, 256 threads, 4x4 micro-tile.                   */
/* W row stride is 4096 (caller pre-offsets the column base).          */
/* ------------------------------------------------------------------ */
__global__ __launch_bounds__(256) void rnn_part(
    const float* __restrict__ A1, const float* __restrict__ W1,
    const float* __restrict__ A2, const float* __restrict__ W2,
    int chunk, int kgHalf, float* __restrict__ part)
{
    __shared__ __align__(16) ull   As [16][66];
    __shared__ __align__(16) float Bsf[16][68];

    const int tid = threadIdx.x;
    const int bn  = blockIdx.x * 64;
    const int kg  = blockIdx.y;

    const float* A; const float* W; int k0;
    if (kg < kgHalf) { A = A1; W = W1; k0 = kg * chunk; }
    else             { A = A2; W = W2; k0 = (kg - kgHalf) * chunk; }

    /* loaders: row = tid>>2 (0..63), k-off = (tid&3)*4 */
    const int lr = tid >> 2;
    const int lk = (tid & 3) * 4;
    const float* arow = A + (size_t)lr * HID + k0;
    const float* brow = W + (size_t)(bn + lr) * 4096 + k0;

    const int tx = tid & 15;
    const int ty = tid >> 4;
    const int n0 = tx * 4;
    const int m0 = ty * 4;

    ull acc[4][2];
#pragma unroll
    for (int i = 0; i < 4; i++) { acc[i][0] = 0ull; acc[i][1] = 0ull; }

    for (int kk = 0; kk < chunk; kk += 16) {
        float4 av = *(const float4*)(arow + kk + lk);
        float4 bv = *(const float4*)(brow + kk + lk);
        __syncthreads();
        As[lk+0][lr] = pk2(av.x, av.x);  As[lk+1][lr] = pk2(av.y, av.y);
        As[lk+2][lr] = pk2(av.z, av.z);  As[lk+3][lr] = pk2(av.w, av.w);
        Bsf[lk+0][lr] = bv.x;  Bsf[lk+1][lr] = bv.y;
        Bsf[lk+2][lr] = bv.z;  Bsf[lk+3][lr] = bv.w;
        __syncthreads();
#pragma unroll
        for (int k = 0; k < 16; k++) {
            longlong2 tb = *(const longlong2*)&Bsf[k][n0];
            longlong2 ta = *(const longlong2*)&As[k][m0];
            longlong2 tc = *(const longlong2*)&As[k][m0 + 2];
            const ull b0 = (ull)tb.x, b1 = (ull)tb.y;
            FMA2(acc[0][0], (ull)ta.x, b0);  FMA2(acc[0][1], (ull)ta.x, b1);
            FMA2(acc[1][0], (ull)ta.y, b0);  FMA2(acc[1][1], (ull)ta.y, b1);
            FMA2(acc[2][0], (ull)tc.x, b0);  FMA2(acc[2][1], (ull)tc.x, b1);
            FMA2(acc[3][0], (ull)tc.y, b0);  FMA2(acc[3][1], (ull)tc.y, b1);
        }
    }

    float* dst = part + (size_t)kg * (BATCH * HID);
#pragma unroll
    for (int mi = 0; mi < 4; mi++) {
        const size_t m = (size_t)(m0 + mi);
#pragma unroll
        for (int nj = 0; nj < 2; nj++) {
            float2 v = upk2(acc[mi][nj]);
            *(float2*)(dst + m * HID + bn + n0 + 2*nj) = v;
        }
    }
}

/* ------------------------------------------------------------------ */
/* Finalize: out = tanh(sum_kg part[kg] + add? + bias?)                */
/* grid 128 x 256 threads, float4 over 64x2048                         */
/* ------------------------------------------------------------------ */
__global__ __launch_bounds__(256) void rnn_fin(
    const float4* __restrict__ part, const float4* __restrict__ add,
    const float* __restrict__ bias, float4* __restrict__ out)
{
    const int i = blockIdx.x * 256 + threadIdx.x;   /* 0 .. 32767 */
    float4 s = part[i];
#pragma unroll
    for (int kg = 1; kg < 8; kg++) {
        float4 p = part[(size_t)kg * (BATCH * HID / 4) + i];
        s.x += p.x; s.y += p.y; s.z += p.z; s.w += p.w;
    }
    if (add) {
        float4 p = add[i];
        s.x += p.x; s.y += p.y; s.z += p.z; s.w += p.w;
    }
    if (bias) {
        const int n = (i & (HID/4 - 1)) * 4;
        s.x += bias[n]; s.y += bias[n+1]; s.z += bias[n+2]; s.w += bias[n+3];
    }
    s.x = tanhf(s.x); s.y = tanhf(s.y); s.z = tanhf(s.z); s.w = tanhf(s.w);
    out[i] = s;
}

/* ------------------------------------------------------------------ */
__global__ void copy_final(const float4* __restrict__ h0,
                           const float4* __restrict__ h1,
                           float4* __restrict__ out)
{
    const int i = blockIdx.x * blockDim.x + threadIdx.x;
    if (i < (BATCH * HID) / 4)            out[i] = h0[i];
    else if (i < (2 * BATCH * HID) / 4)   out[i] = h1[i - (BATCH * HID) / 4];
}

/* ------------------------------------------------------------------ */
extern "C" void kernel_launch(void* const* d_in, const int* in_sizes, int n_in,
                              void* d_out, int out_size)
{
    (void)in_sizes; (void)n_in; (void)out_size;

    const void*  inputs = d_in[0];
    const float* hidden = (const float*)d_in[1];
    const float* emb    = (const float*)d_in[2];
    const float* W0     = (const float*)d_in[3];
    const float* b0     = (const float*)d_in[4];
    const float* W1     = (const float*)d_in[5];
    const float* b1     = (const float*)d_in[6];
    const float* Wout   = (const float*)d_in[7];
    const float* bout   = (const float*)d_in[8];
    float* out = (float*)d_out;

    float *pX0, *pH, *ph0, *pPart;
    cudaGetSymbolAddress((void**)&pX0,   g_X0);
    cudaGetSymbolAddress((void**)&pH,    g_H);
    cudaGetSymbolAddress((void**)&ph0,   g_h0);
    cudaGetSymbolAddress((void**)&pPart, g_part);

    detect_idx_kernel<<<1, 32>>>((const unsigned int*)inputs);

    /* X0 = emb_table[inputs] @ W0x^T + b0 */
    {
        dim3 g(HID / 128, MB_ / 128);   /* 16 x 64 */
        gemm_big<<<g, 256>>>(emb, inputs, EMB,
                             W0, EMB + HID, b0,
                             pX0, HID, HID, EMB);
    }

    const dim3 gp(HID / 64, 8);   /* 32 x 8 = 256 blocks */

    for (int t = 0; t < T_SEQ; t++) {
        const float* h0src = t ? (ph0 + ((t - 1) & 1) * (BATCH * HID)) : hidden;
        float*       h0dst = ph0 + (t & 1) * (BATCH * HID);
        const float* h1src = t ? (pH + (size_t)(t - 1) * BATCH * HID)
                               : (hidden + BATCH * HID);
        float*       h1dst = pH + (size_t)t * BATCH * HID;

        /* layer 0: tanh(X0[t] + h0 @ W0h^T)  (b0 already in X0) */
        rnn_part<<<gp, 256>>>(h0src, W0 + EMB, (const float*)0, (const float*)0,
                              HID / 8, 8, pPart);
        rnn_fin<<<128, 256>>>((const float4*)pPart,
                              (const float4*)(pX0 + (size_t)t * BATCH * HID),
                              (const float*)0, (float4*)h0dst);

        /* layer 1: tanh(h0' @ W1x^T + h1 @ W1h^T + b1) */
        rnn_part<<<gp, 256>>>(h0dst, W1, h1src, W1 + HID,
                              HID / 4, 4, pPart);
        rnn_fin<<<128, 256>>>((const float4*)pPart, (const float4*)0,
                              b1, (float4*)h1dst);
    }

    /* logits = H @ Wout^T + bout */
    {
        dim3 g((VOCAB + 127) / 128, MB_ / 128);   /* 79 x 64 */
        gemm_big<<<g, 256>>>(pH, (const void*)0, HID,
                             Wout, HID, bout,
                             out, VOCAB, VOCAB, HID);
    }

    copy_final<<<256, 256>>>(
        (const float4*)(ph0 + ((T_SEQ - 1) & 1) * (BATCH * HID)),
        (const float4*)(pH + (size_t)(T_SEQ - 1) * BATCH * HID),
        (float4*)(out + (size_t)MB_ * VOCAB));
}

// round 7
// speedup vs baseline: 2.5330x; 1.3076x over previous
#include <cuda_runtime.h>
#include <cuda_bf16.h>
#include <math.h>
#include <stdint.h>

typedef unsigned long long ull;

#define T_SEQ 128
#define BATCH 64
#define EMB   2048
#define HID   2048
#define VOCAB 10000
#define MB_   (T_SEQ * BATCH)   /* 8192 */
#define BH    (BATCH * HID)     /* 131072 */

/* ------------------------------------------------------------------ */
/* Scratch (device globals only)                                       */
/* ------------------------------------------------------------------ */
__device__ float g_X0[(size_t)MB_ * HID];
__device__ float g_H [(size_t)MB_ * HID];
__device__ float g_h0[2][BH];
__device__ float g_part[8][BH];
__device__ int   g_cnt[32];
__device__ int   g_is64;

__device__ __nv_bfloat16 g_emb_hi [(size_t)VOCAB * EMB];
__device__ __nv_bfloat16 g_emb_lo [(size_t)VOCAB * EMB];
__device__ __nv_bfloat16 g_w0x_hi [(size_t)HID * EMB];
__device__ __nv_bfloat16 g_w0x_lo [(size_t)HID * EMB];
__device__ __nv_bfloat16 g_wout_hi[(size_t)VOCAB * HID];
__device__ __nv_bfloat16 g_wout_lo[(size_t)VOCAB * HID];
__device__ __nv_bfloat16 g_h_hi   [(size_t)MB_ * HID];
__device__ __nv_bfloat16 g_h_lo   [(size_t)MB_ * HID];

/* ------------------------------------------------------------------ */
/* f32x2 helpers (recurrence kernel)                                   */
/* ------------------------------------------------------------------ */
__device__ __forceinline__ ull pk2(float x, float y) {
    ull r; asm("mov.b64 %0, {%1,%2};" : "=l"(r) : "f"(x), "f"(y)); return r;
}
__device__ __forceinline__ float2 upk2(ull v) {
    float2 r; asm("mov.b64 {%0,%1}, %2;" : "=f"(r.x), "=f"(r.y) : "l"(v)); return r;
}
#define FMA2(acc, a, b) asm("fma.rn.f32x2 %0, %1, %2, %0;" : "+l"(acc) : "l"(a), "l"(b))

__device__ __forceinline__ uint32_t s2u(const void* p) {
    uint32_t a;
    asm("{ .reg .u64 t; cvta.to.shared.u64 t, %1; cvt.u32.u64 %0, t; }"
        : "=r"(a) : "l"(p));
    return a;
}

/* ------------------------------------------------------------------ */
/* mma.sync / ldmatrix / cp.async helpers (compute_103-safe, sm_80+)   */
/* ------------------------------------------------------------------ */
__device__ __forceinline__ void ldm_x4(uint32_t& r0, uint32_t& r1,
                                       uint32_t& r2, uint32_t& r3, uint32_t a) {
    asm volatile("ldmatrix.sync.aligned.m8n8.x4.shared.b16 {%0,%1,%2,%3}, [%4];"
                 : "=r"(r0), "=r"(r1), "=r"(r2), "=r"(r3) : "r"(a));
}
__device__ __forceinline__ void mma16816(float* c, const uint32_t* a,
                                         const uint32_t* b) {
    asm volatile(
        "mma.sync.aligned.m16n8k16.row.col.f32.bf16.bf16.f32 "
        "{%0,%1,%2,%3}, {%4,%5,%6,%7}, {%8,%9}, {%0,%1,%2,%3};"
        : "+f"(c[0]), "+f"(c[1]), "+f"(c[2]), "+f"(c[3])
        : "r"(a[0]), "r"(a[1]), "r"(a[2]), "r"(a[3]), "r"(b[0]), "r"(b[1]));
}
__device__ __forceinline__ void cpa16(uint32_t dst, const void* src, int srcsz) {
    asm volatile("cp.async.cg.shared.global [%0], [%1], 16, %2;"
                 :: "r"(dst), "l"(src), "r"(srcsz) : "memory");
}
__device__ __forceinline__ void cpa_commit() {
    asm volatile("cp.async.commit_group;" ::: "memory");
}

/* ------------------------------------------------------------------ */
__global__ void detect_idx_kernel(const unsigned int* __restrict__ p) {
    if (threadIdx.x == 0) {
        unsigned int o = 0;
#pragma unroll
        for (int i = 0; i < 16; i++) o |= p[2 * i + 1];
        g_is64 = (o == 0u) ? 1 : 0;
    }
}

/* ------------------------------------------------------------------ */
/* fp32 -> bf16 hi/lo split                                            */
/* ------------------------------------------------------------------ */
__global__ void conv_split(const float4* __restrict__ src, long n4,
                           int c4s, int ld4s,
                           __nv_bfloat162* __restrict__ hi,
                           __nv_bfloat162* __restrict__ lo)
{
    long i = (long)blockIdx.x * 256 + threadIdx.x;
    if (i >= n4) return;
    long r = i >> c4s;
    long c = i & ((1L << c4s) - 1);
    float4 v = src[(r << ld4s) + c];
    __nv_bfloat16 hx = __float2bfloat16(v.x), hy = __float2bfloat16(v.y);
    __nv_bfloat16 hz = __float2bfloat16(v.z), hw = __float2bfloat16(v.w);
    __nv_bfloat162 h0; h0.x = hx; h0.y = hy;
    __nv_bfloat162 h1; h1.x = hz; h1.y = hw;
    hi[2 * i] = h0; hi[2 * i + 1] = h1;
    __nv_bfloat162 l0, l1;
    l0.x = __float2bfloat16(v.x - __bfloat162float(hx));
    l0.y = __float2bfloat16(v.y - __bfloat162float(hy));
    l1.x = __float2bfloat16(v.z - __bfloat162float(hz));
    l1.y = __float2bfloat16(v.w - __bfloat162float(hw));
    lo[2 * i] = l0; lo[2 * i + 1] = l1;
}

/* ------------------------------------------------------------------ */
/* mma.sync bf16 3-pass split GEMM:                                    */
/*   C[M,N] = A[M,K=2048] * B[N,K]^T + bias  (A rows optional gather)  */
/* Tile 128x128, BK=32, 256 thr (8 warps: 4m x 2n, warp 32x64).        */
/* cp.async double-buffered smem: per stage Ahi/Alo/Bhi/Blo            */
/*   each [128 rows][32 bf16, 80B padded stride] = 10240B.             */
/* ------------------------------------------------------------------ */
#define ROWB   80
#define R_AHI  0
#define R_ALO  10240
#define R_BHI  20480
#define R_BLO  30720
#define STAGEB 40960
#define GEMM_SMEM (2 * STAGEB)

__global__ __launch_bounds__(256, 1) void gemm_mma(
    const __nv_bfloat16* __restrict__ Ahi, const __nv_bfloat16* __restrict__ Alo,
    const void* __restrict__ aidx,
    const __nv_bfloat16* __restrict__ Bhi, const __nv_bfloat16* __restrict__ Blo,
    int nrowsB, const float* __restrict__ bias,
    float* __restrict__ C, int ldc, int ncols)
{
    extern __shared__ char smem[];
    const uint32_t smbase = s2u(smem);

    const int tid  = threadIdx.x;
    const int lane = tid & 31;
    const int wid  = tid >> 5;
    const int wm   = wid & 3;          /* 4 m-groups of 32 rows */
    const int wn   = wid >> 2;         /* 2 n-groups of 64 cols */
    const int bm   = blockIdx.y * 128;
    const int bn   = blockIdx.x * 128;

    /* ---- loader mapping: row = tid>>1, chunk pair = (tid&1)*2 ---- */
    const int lrow  = tid >> 1;
    const int cpair = (tid & 1) * 2;
    const uint32_t dstOff = (uint32_t)(lrow * ROWB + cpair * 16);

    size_t aoff;
    {
        const int m = bm + lrow;
        size_t row;
        if (aidx) {
            if (g_is64) row = (size_t)((const long long*)aidx)[m];
            else        row = (size_t)((const int*)aidx)[m];
        } else row = (size_t)m;
        aoff = row * 2048 + (size_t)cpair * 8;
    }
    const int  nrow = bn + lrow;
    const int  bsz  = (nrow < nrowsB) ? 16 : 0;
    const size_t boff = (size_t)((nrow < nrowsB) ? nrow : 0) * 2048
                      + (size_t)cpair * 8;

    /* ---- ldmatrix per-lane geometry ---- */
    const int rlane  = lane & 15;
    const int khalf2 = (lane >> 4) * 16;    /* byte offset of k-half */
    uint32_t rowA[2], rowB[4];
#pragma unroll
    for (int mt = 0; mt < 2; mt++)
        rowA[mt] = (uint32_t)((wm * 32 + mt * 16 + rlane) * ROWB);
#pragma unroll
    for (int nt = 0; nt < 4; nt++)
        rowB[nt] = (uint32_t)((wn * 64 + nt * 16 + rlane) * ROWB);

    float acc[2][8][4];
#pragma unroll
    for (int mt = 0; mt < 2; mt++)
#pragma unroll
        for (int j = 0; j < 8; j++)
#pragma unroll
            for (int q = 0; q < 4; q++) acc[mt][j][q] = 0.f;

    const int NIT = 2048 / 32;   /* 64 */

    /* issue stage loads for iteration `it` */
    auto issue = [&](int it) {
        const uint32_t sb = smbase + (uint32_t)(it & 1) * STAGEB;
        const size_t kb = (size_t)it * 32;
        cpa16(sb + R_AHI + dstOff,      Ahi + aoff + kb,     16);
        cpa16(sb + R_AHI + dstOff + 16, Ahi + aoff + kb + 8, 16);
        cpa16(sb + R_ALO + dstOff,      Alo + aoff + kb,     16);
        cpa16(sb + R_ALO + dstOff + 16, Alo + aoff + kb + 8, 16);
        cpa16(sb + R_BHI + dstOff,      Bhi + boff + kb,     bsz);
        cpa16(sb + R_BHI + dstOff + 16, Bhi + boff + kb + 8, bsz);
        cpa16(sb + R_BLO + dstOff,      Blo + boff + kb,     bsz);
        cpa16(sb + R_BLO + dstOff + 16, Blo + boff + kb + 8, bsz);
        cpa_commit();
    };

    issue(0);

    for (int it = 0; it < NIT; it++) {
        if (it + 1 < NIT) {
            issue(it + 1);
            asm volatile("cp.async.wait_group 1;" ::: "memory");
        } else {
            asm volatile("cp.async.wait_group 0;" ::: "memory");
        }
        __syncthreads();

        const uint32_t sb = smbase + (uint32_t)(it & 1) * STAGEB;
#pragma unroll
        for (int kk = 0; kk < 2; kk++) {
            const uint32_t kbyt = (uint32_t)(kk * 32 + khalf2);
            uint32_t ah[2][4], al[2][4];
#pragma unroll
            for (int mt = 0; mt < 2; mt++) {
                ldm_x4(ah[mt][0], ah[mt][1], ah[mt][2], ah[mt][3],
                       sb + R_AHI + rowA[mt] + kbyt);
                ldm_x4(al[mt][0], al[mt][1], al[mt][2], al[mt][3],
                       sb + R_ALO + rowA[mt] + kbyt);
            }
            uint32_t bh[8][2], bl[8][2];
#pragma unroll
            for (int nt = 0; nt < 4; nt++) {
                uint32_t t0, t1, t2, t3;
                ldm_x4(t0, t1, t2, t3, sb + R_BHI + rowB[nt] + kbyt);
                bh[2*nt][0] = t0; bh[2*nt][1] = t2;
                bh[2*nt+1][0] = t1; bh[2*nt+1][1] = t3;
                ldm_x4(t0, t1, t2, t3, sb + R_BLO + rowB[nt] + kbyt);
                bl[2*nt][0] = t0; bl[2*nt][1] = t2;
                bl[2*nt+1][0] = t1; bl[2*nt+1][1] = t3;
            }
#pragma unroll
            for (int mt = 0; mt < 2; mt++)
#pragma unroll
                for (int j = 0; j < 8; j++) {
                    mma16816(acc[mt][j], ah[mt], bh[j]);
                    mma16816(acc[mt][j], ah[mt], bl[j]);
                    mma16816(acc[mt][j], al[mt], bh[j]);
                }
        }
        __syncthreads();
    }

    /* ---- epilogue ---- */
    const int gid = lane >> 2;
    const int tig = lane & 3;
#pragma unroll
    for (int mt = 0; mt < 2; mt++) {
#pragma unroll
        for (int j = 0; j < 8; j++) {
            const int col = bn + wn * 64 + j * 8 + tig * 2;
            if (col < ncols) {
                const float bx = bias[col], by = bias[col + 1];
                const size_t r0 = (size_t)(bm + wm * 32 + mt * 16 + gid);
                const size_t r1 = r0 + 8;
                float2 v0 = make_float2(acc[mt][j][0] + bx, acc[mt][j][1] + by);
                float2 v1 = make_float2(acc[mt][j][2] + bx, acc[mt][j][3] + by);
                *(float2*)(C + r0 * (size_t)ldc + col) = v0;
                *(float2*)(C + r1 * (size_t)ldc + col) = v1;
            }
        }
    }
}

/* ------------------------------------------------------------------ */
/* Recurrent step partial GEMM (split-K) with fused last-block         */
/* finalize (sum 8 partials (+Xadd)(+bias) -> tanh -> fp32 h and       */
/* optional bf16 hi/lo mirror).                                        */
/* ------------------------------------------------------------------ */
__global__ __launch_bounds__(256) void rnn_part(
    const float* __restrict__ A1, const float* __restrict__ W1,
    const float* __restrict__ A2, const float* __restrict__ W2,
    int chunk, int kgHalf, float* __restrict__ part,
    const float4* __restrict__ Xadd, const float* __restrict__ bias,
    float* __restrict__ outF,
    __nv_bfloat162* __restrict__ outHi, __nv_bfloat162* __restrict__ outLo)
{
    __shared__ __align__(16) ull   As [16][66];
    __shared__ __align__(16) float Bsf[16][68];
    __shared__ int s_last;

    const int tid = threadIdx.x;
    const int bn  = blockIdx.x * 64;
    const int kg  = blockIdx.y;

    const float* A; const float* W; int k0;
    if (kg < kgHalf) { A = A1; W = W1; k0 = kg * chunk; }
    else             { A = A2; W = W2; k0 = (kg - kgHalf) * chunk; }

    const int lr = tid >> 2;
    const int lk = (tid & 3) * 4;
    const float* arow = A + (size_t)lr * HID + k0;
    const float* brow = W + (size_t)(bn + lr) * 4096 + k0;

    const int tx = tid & 15;
    const int ty = tid >> 4;
    const int n0 = tx * 4;
    const int m0 = ty * 4;

    ull acc[4][2];
#pragma unroll
    for (int i = 0; i < 4; i++) { acc[i][0] = 0ull; acc[i][1] = 0ull; }

    for (int kk = 0; kk < chunk; kk += 16) {
        float4 av = *(const float4*)(arow + kk + lk);
        float4 bv = *(const float4*)(brow + kk + lk);
        __syncthreads();
        As[lk+0][lr] = pk2(av.x, av.x);  As[lk+1][lr] = pk2(av.y, av.y);
        As[lk+2][lr] = pk2(av.z, av.z);  As[lk+3][lr] = pk2(av.w, av.w);
        Bsf[lk+0][lr] = bv.x;  Bsf[lk+1][lr] = bv.y;
        Bsf[lk+2][lr] = bv.z;  Bsf[lk+3][lr] = bv.w;
        __syncthreads();
#pragma unroll
        for (int k = 0; k < 16; k++) {
            longlong2 tb  = *(const longlong2*)&Bsf[k][n0];
            longlong2 ta  = *(const longlong2*)&As[k][m0];
            longlong2 tc2 = *(const longlong2*)&As[k][m0 + 2];
            const ull b0 = (ull)tb.x, b1 = (ull)tb.y;
            FMA2(acc[0][0], (ull)ta.x,  b0);  FMA2(acc[0][1], (ull)ta.x,  b1);
            FMA2(acc[1][0], (ull)ta.y,  b0);  FMA2(acc[1][1], (ull)ta.y,  b1);
            FMA2(acc[2][0], (ull)tc2.x, b0);  FMA2(acc[2][1], (ull)tc2.x, b1);
            FMA2(acc[3][0], (ull)tc2.y, b0);  FMA2(acc[3][1], (ull)tc2.y, b1);
        }
    }

    float* dst = part + (size_t)kg * BH;
#pragma unroll
    for (int mi = 0; mi < 4; mi++) {
        const size_t m = (size_t)(m0 + mi);
#pragma unroll
        for (int nj = 0; nj < 2; nj++) {
            float2 v = upk2(acc[mi][nj]);
            *(float2*)(dst + m * HID + bn + n0 + 2*nj) = v;
        }
    }

    /* last-block finalize for this 64-col strip */
    __threadfence();
    if (tid == 0) {
        int old = atomicAdd(&g_cnt[blockIdx.x], 1);
        s_last = (old == 7) ? 1 : 0;
    }
    __syncthreads();
    if (!s_last) return;
    __threadfence();

    const float4* p4 = (const float4*)part;
    float4* o4 = (float4*)outF;
    for (int u = tid; u < 1024; u += 256) {          /* 64 rows x 16 float4 */
        const int m  = u >> 4;
        const int c4 = u & 15;
        const size_t off = (size_t)m * (HID / 4) + (bn >> 2) + c4;
        float4 sv = p4[off];
#pragma unroll
        for (int kg2 = 1; kg2 < 8; kg2++) {
            float4 p = p4[(size_t)kg2 * (BH / 4) + off];
            sv.x += p.x; sv.y += p.y; sv.z += p.z; sv.w += p.w;
        }
        if (Xadd) {
            float4 p = Xadd[off];
            sv.x += p.x; sv.y += p.y; sv.z += p.z; sv.w += p.w;
        }
        if (bias) {
            const int n = bn + c4 * 4;
            sv.x += bias[n]; sv.y += bias[n+1]; sv.z += bias[n+2]; sv.w += bias[n+3];
        }
        sv.x = tanhf(sv.x); sv.y = tanhf(sv.y);
        sv.z = tanhf(sv.z); sv.w = tanhf(sv.w);
        o4[off] = sv;
        if (outHi) {
            __nv_bfloat16 hx = __float2bfloat16(sv.x), hy = __float2bfloat16(sv.y);
            __nv_bfloat16 hz = __float2bfloat16(sv.z), hw = __float2bfloat16(sv.w);
            __nv_bfloat162 a; a.x = hx; a.y = hy;
            __nv_bfloat162 b; b.x = hz; b.y = hw;
            outHi[2 * off] = a; outHi[2 * off + 1] = b;
            __nv_bfloat162 la, lb;
            la.x = __float2bfloat16(sv.x - __bfloat162float(hx));
            la.y = __float2bfloat16(sv.y - __bfloat162float(hy));
            lb.x = __float2bfloat16(sv.z - __bfloat162float(hz));
            lb.y = __float2bfloat16(sv.w - __bfloat162float(hw));
            outLo[2 * off] = la; outLo[2 * off + 1] = lb;
        }
    }
    __threadfence();
    __syncthreads();
    if (tid == 0) g_cnt[blockIdx.x] = 0;
}

/* ------------------------------------------------------------------ */
__global__ void copy_final(const float4* __restrict__ h0,
                           const float4* __restrict__ h1,
                           float4* __restrict__ out)
{
    const int i = blockIdx.x * blockDim.x + threadIdx.x;
    if (i < BH / 4)           out[i] = h0[i];
    else if (i < 2 * BH / 4)  out[i] = h1[i - BH / 4];
}

/* ------------------------------------------------------------------ */
extern "C" void kernel_launch(void* const* d_in, const int* in_sizes, int n_in,
                              void* d_out, int out_size)
{
    (void)in_sizes; (void)n_in; (void)out_size;

    const void*  inputs = d_in[0];
    const float* hidden = (const float*)d_in[1];
    const float* emb    = (const float*)d_in[2];
    const float* W0     = (const float*)d_in[3];
    const float* b0     = (const float*)d_in[4];
    const float* W1     = (const float*)d_in[5];
    const float* b1     = (const float*)d_in[6];
    const float* Wout   = (const float*)d_in[7];
    const float* bout   = (const float*)d_in[8];
    float* out = (float*)d_out;

    float *pX0, *pH, *ph0, *pPart;
    __nv_bfloat16 *pEh, *pEl, *pWxh, *pWxl, *pWoh, *pWol, *pHh, *pHl;
    cudaGetSymbolAddress((void**)&pX0,   g_X0);
    cudaGetSymbolAddress((void**)&pH,    g_H);
    cudaGetSymbolAddress((void**)&ph0,   g_h0);
    cudaGetSymbolAddress((void**)&pPart, g_part);
    cudaGetSymbolAddress((void**)&pEh,   g_emb_hi);
    cudaGetSymbolAddress((void**)&pEl,   g_emb_lo);
    cudaGetSymbolAddress((void**)&pWxh,  g_w0x_hi);
    cudaGetSymbolAddress((void**)&pWxl,  g_w0x_lo);
    cudaGetSymbolAddress((void**)&pWoh,  g_wout_hi);
    cudaGetSymbolAddress((void**)&pWol,  g_wout_lo);
    cudaGetSymbolAddress((void**)&pHh,   g_h_hi);
    cudaGetSymbolAddress((void**)&pHl,   g_h_lo);

    static int smem_set = 0;
    if (!smem_set) {
        cudaFuncSetAttribute(gemm_mma, cudaFuncAttributeMaxDynamicSharedMemorySize,
                             GEMM_SMEM);
        smem_set = 1;
    }

    detect_idx_kernel<<<1, 32>>>((const unsigned int*)inputs);

    /* weight / embedding hi-lo conversions */
    {
        long n4e = (long)VOCAB * (EMB / 4);
        conv_split<<<(unsigned)((n4e + 255) / 256), 256>>>(
            (const float4*)emb, n4e, 9, 9,
            (__nv_bfloat162*)pEh, (__nv_bfloat162*)pEl);
        long n4o = (long)VOCAB * (HID / 4);
        conv_split<<<(unsigned)((n4o + 255) / 256), 256>>>(
            (const float4*)Wout, n4o, 9, 9,
            (__nv_bfloat162*)pWoh, (__nv_bfloat162*)pWol);
        long n4w = (long)HID * (EMB / 4);        /* W0 cols 0..2047, ld 4096 */
        conv_split<<<(unsigned)((n4w + 255) / 256), 256>>>(
            (const float4*)W0, n4w, 9, 10,
            (__nv_bfloat162*)pWxh, (__nv_bfloat162*)pWxl);
    }

    /* X0 = emb[inputs] @ W0x^T + b0   (mma.sync bf16-split) */
    {
        dim3 g(HID / 128, MB_ / 128);   /* 16 x 64 */
        gemm_mma<<<g, 256, GEMM_SMEM>>>(pEh, pEl, inputs,
                                        pWxh, pWxl, HID, b0,
                                        pX0, HID, HID);
    }

    /* sequential scan: 2 launches per step (finalize fused) */
    const dim3 gp(HID / 64, 8);
    for (int t = 0; t < T_SEQ; t++) {
        const float* h0src = t ? (ph0 + ((t - 1) & 1) * BH) : hidden;
        float*       h0dst = ph0 + (t & 1) * BH;
        const float* h1src = t ? (pH + (size_t)(t - 1) * BH) : (hidden + BH);
        float*       h1dst = pH + (size_t)t * BH;

        rnn_part<<<gp, 256>>>(h0src, W0 + EMB, (const float*)0, (const float*)0,
                              HID / 8, 8, pPart,
                              (const float4*)(pX0 + (size_t)t * BH), (const float*)0,
                              h0dst, (__nv_bfloat162*)0, (__nv_bfloat162*)0);

        rnn_part<<<gp, 256>>>(h0dst, W1, h1src, W1 + HID,
                              HID / 4, 4, pPart,
                              (const float4*)0, b1,
                              h1dst,
                              (__nv_bfloat162*)(pHh + (size_t)t * BH),
                              (__nv_bfloat162*)(pHl + (size_t)t * BH));
    }

    /* logits = H @ Wout^T + bout   (mma.sync bf16-split) */
    {
        dim3 g((VOCAB + 127) / 128, MB_ / 128);   /* 79 x 64 */
        gemm_mma<<<g, 256, GEMM_SMEM>>>(pHh, pHl, (const void*)0,
                                        pWoh, pWol, VOCAB, bout,
                                        out, VOCAB, VOCAB);
    }

    copy_final<<<256, 256>>>(
        (const float4*)(ph0 + ((T_SEQ - 1) & 1) * BH),
        (const float4*)(pH + (size_t)(T_SEQ - 1) * BH),
        (float4*)(out + (size_t)MB_ * VOCAB));
}

// round 8
// speedup vs baseline: 4.3870x; 1.7320x over previous
#include <cuda_runtime.h>
#include <cuda_bf16.h>
#include <math.h>
#include <stdint.h>

#define T_SEQ 128
#define BATCH 64
#define EMB   2048
#define HID   2048
#define VOCAB 10000
#define MB_   (T_SEQ * BATCH)   /* 8192 */
#define BH    (BATCH * HID)     /* 131072 */

/* ------------------------------------------------------------------ */
/* Scratch (device globals only)                                       */
/* ------------------------------------------------------------------ */
__device__ float g_X0[(size_t)MB_ * HID];    /* emb@W0x^T + b0          */
__device__ float g_X1[(size_t)MB_ * HID];    /* H0@W1x^T + b1           */
__device__ float g_part[8][BH];              /* split-K partials        */
__device__ int   g_cnt[32];
__device__ int   g_is64;

__device__ __nv_bfloat16 g_emb_hi [(size_t)VOCAB * EMB];
__device__ __nv_bfloat16 g_emb_lo [(size_t)VOCAB * EMB];
__device__ __nv_bfloat16 g_w0x_hi [(size_t)HID * HID];
__device__ __nv_bfloat16 g_w0x_lo [(size_t)HID * HID];
__device__ __nv_bfloat16 g_w0h_hi [(size_t)HID * HID];
__device__ __nv_bfloat16 g_w0h_lo [(size_t)HID * HID];
__device__ __nv_bfloat16 g_w1x_hi [(size_t)HID * HID];
__device__ __nv_bfloat16 g_w1x_lo [(size_t)HID * HID];
__device__ __nv_bfloat16 g_w1h_hi [(size_t)HID * HID];
__device__ __nv_bfloat16 g_w1h_lo [(size_t)HID * HID];
__device__ __nv_bfloat16 g_wout_hi[(size_t)VOCAB * HID];
__device__ __nv_bfloat16 g_wout_lo[(size_t)VOCAB * HID];
__device__ __nv_bfloat16 g_H0_hi  [(size_t)MB_ * HID];
__device__ __nv_bfloat16 g_H0_lo  [(size_t)MB_ * HID];
__device__ __nv_bfloat16 g_H1_hi  [(size_t)MB_ * HID];
__device__ __nv_bfloat16 g_H1_lo  [(size_t)MB_ * HID];
__device__ __nv_bfloat16 g_hin_hi [2 * BH];
__device__ __nv_bfloat16 g_hin_lo [2 * BH];

/* ------------------------------------------------------------------ */
__device__ __forceinline__ uint32_t s2u(const void* p) {
    uint32_t a;
    asm("{ .reg .u64 t; cvta.to.shared.u64 t, %1; cvt.u32.u64 %0, t; }"
        : "=r"(a) : "l"(p));
    return a;
}
__device__ __forceinline__ void ldm_x4(uint32_t& r0, uint32_t& r1,
                                       uint32_t& r2, uint32_t& r3, uint32_t a) {
    asm volatile("ldmatrix.sync.aligned.m8n8.x4.shared.b16 {%0,%1,%2,%3}, [%4];"
                 : "=r"(r0), "=r"(r1), "=r"(r2), "=r"(r3) : "r"(a));
}
__device__ __forceinline__ void mma16816(float* c, const uint32_t* a,
                                         const uint32_t* b) {
    asm volatile(
        "mma.sync.aligned.m16n8k16.row.col.f32.bf16.bf16.f32 "
        "{%0,%1,%2,%3}, {%4,%5,%6,%7}, {%8,%9}, {%0,%1,%2,%3};"
        : "+f"(c[0]), "+f"(c[1]), "+f"(c[2]), "+f"(c[3])
        : "r"(a[0]), "r"(a[1]), "r"(a[2]), "r"(a[3]), "r"(b[0]), "r"(b[1]));
}
__device__ __forceinline__ void cpa16(uint32_t dst, const void* src, int srcsz) {
    asm volatile("cp.async.cg.shared.global [%0], [%1], 16, %2;"
                 :: "r"(dst), "l"(src), "r"(srcsz) : "memory");
}
__device__ __forceinline__ void cpa_commit() {
    asm volatile("cp.async.commit_group;" ::: "memory");
}

/* ------------------------------------------------------------------ */
__global__ void detect_idx_kernel(const unsigned int* __restrict__ p) {
    if (threadIdx.x == 0) {
        unsigned int o = 0;
#pragma unroll
        for (int i = 0; i < 16; i++) o |= p[2 * i + 1];
        g_is64 = (o == 0u) ? 1 : 0;
    }
}

/* ------------------------------------------------------------------ */
/* fp32 -> bf16 hi/lo split                                            */
/* ------------------------------------------------------------------ */
__global__ void conv_split(const float4* __restrict__ src, long n4,
                           int c4s, int ld4s,
                           __nv_bfloat162* __restrict__ hi,
                           __nv_bfloat162* __restrict__ lo)
{
    long i = (long)blockIdx.x * 256 + threadIdx.x;
    if (i >= n4) return;
    long r = i >> c4s;
    long c = i & ((1L << c4s) - 1);
    float4 v = src[(r << ld4s) + c];
    __nv_bfloat16 hx = __float2bfloat16(v.x), hy = __float2bfloat16(v.y);
    __nv_bfloat16 hz = __float2bfloat16(v.z), hw = __float2bfloat16(v.w);
    __nv_bfloat162 h0; h0.x = hx; h0.y = hy;
    __nv_bfloat162 h1; h1.x = hz; h1.y = hw;
    hi[2 * i] = h0; hi[2 * i + 1] = h1;
    __nv_bfloat162 l0, l1;
    l0.x = __float2bfloat16(v.x - __bfloat162float(hx));
    l0.y = __float2bfloat16(v.y - __bfloat162float(hy));
    l1.x = __float2bfloat16(v.z - __bfloat162float(hz));
    l1.y = __float2bfloat16(v.w - __bfloat162float(hw));
    lo[2 * i] = l0; lo[2 * i + 1] = l1;
}

/* ------------------------------------------------------------------ */
/* Big mma.sync bf16 3-pass GEMM (unchanged from R7):                  */
/*   C[M,N] = A[M,K=2048] * B[N,K]^T + bias                            */
/* ------------------------------------------------------------------ */
#define ROWB   80
#define R_AHI  0
#define R_ALO  10240
#define R_BHI  20480
#define R_BLO  30720
#define STAGEB 40960
#define GEMM_SMEM (2 * STAGEB)

__global__ __launch_bounds__(256, 1) void gemm_mma(
    const __nv_bfloat16* __restrict__ Ahi, const __nv_bfloat16* __restrict__ Alo,
    const void* __restrict__ aidx,
    const __nv_bfloat16* __restrict__ Bhi, const __nv_bfloat16* __restrict__ Blo,
    int nrowsB, const float* __restrict__ bias,
    float* __restrict__ C, int ldc, int ncols)
{
    extern __shared__ char smem[];
    const uint32_t smbase = s2u(smem);

    const int tid  = threadIdx.x;
    const int lane = tid & 31;
    const int wid  = tid >> 5;
    const int wm   = wid & 3;
    const int wn   = wid >> 2;
    const int bm   = blockIdx.y * 128;
    const int bn   = blockIdx.x * 128;

    const int lrow  = tid >> 1;
    const int cpair = (tid & 1) * 2;
    const uint32_t dstOff = (uint32_t)(lrow * ROWB + cpair * 16);

    size_t aoff;
    {
        const int m = bm + lrow;
        size_t row;
        if (aidx) {
            if (g_is64) row = (size_t)((const long long*)aidx)[m];
            else        row = (size_t)((const int*)aidx)[m];
        } else row = (size_t)m;
        aoff = row * 2048 + (size_t)cpair * 8;
    }
    const int  nrow = bn + lrow;
    const int  bsz  = (nrow < nrowsB) ? 16 : 0;
    const size_t boff = (size_t)((nrow < nrowsB) ? nrow : 0) * 2048
                      + (size_t)cpair * 8;

    const int rlane  = lane & 15;
    const int khalf2 = (lane >> 4) * 16;
    uint32_t rowA[2], rowB[4];
#pragma unroll
    for (int mt = 0; mt < 2; mt++)
        rowA[mt] = (uint32_t)((wm * 32 + mt * 16 + rlane) * ROWB);
#pragma unroll
    for (int nt = 0; nt < 4; nt++)
        rowB[nt] = (uint32_t)((wn * 64 + nt * 16 + rlane) * ROWB);

    float acc[2][8][4];
#pragma unroll
    for (int mt = 0; mt < 2; mt++)
#pragma unroll
        for (int j = 0; j < 8; j++)
#pragma unroll
            for (int q = 0; q < 4; q++) acc[mt][j][q] = 0.f;

    const int NIT = 2048 / 32;

    auto issue = [&](int it) {
        const uint32_t sb = smbase + (uint32_t)(it & 1) * STAGEB;
        const size_t kb = (size_t)it * 32;
        cpa16(sb + R_AHI + dstOff,      Ahi + aoff + kb,     16);
        cpa16(sb + R_AHI + dstOff + 16, Ahi + aoff + kb + 8, 16);
        cpa16(sb + R_ALO + dstOff,      Alo + aoff + kb,     16);
        cpa16(sb + R_ALO + dstOff + 16, Alo + aoff + kb + 8, 16);
        cpa16(sb + R_BHI + dstOff,      Bhi + boff + kb,     bsz);
        cpa16(sb + R_BHI + dstOff + 16, Bhi + boff + kb + 8, bsz);
        cpa16(sb + R_BLO + dstOff,      Blo + boff + kb,     bsz);
        cpa16(sb + R_BLO + dstOff + 16, Blo + boff + kb + 8, bsz);
        cpa_commit();
    };

    issue(0);

    for (int it = 0; it < NIT; it++) {
        if (it + 1 < NIT) {
            issue(it + 1);
            asm volatile("cp.async.wait_group 1;" ::: "memory");
        } else {
            asm volatile("cp.async.wait_group 0;" ::: "memory");
        }
        __syncthreads();

        const uint32_t sb = smbase + (uint32_t)(it & 1) * STAGEB;
#pragma unroll
        for (int kk = 0; kk < 2; kk++) {
            const uint32_t kbyt = (uint32_t)(kk * 32 + khalf2);
            uint32_t ah[2][4], al[2][4];
#pragma unroll
            for (int mt = 0; mt < 2; mt++) {
                ldm_x4(ah[mt][0], ah[mt][1], ah[mt][2], ah[mt][3],
                       sb + R_AHI + rowA[mt] + kbyt);
                ldm_x4(al[mt][0], al[mt][1], al[mt][2], al[mt][3],
                       sb + R_ALO + rowA[mt] + kbyt);
            }
            uint32_t bh[8][2], bl[8][2];
#pragma unroll
            for (int nt = 0; nt < 4; nt++) {
                uint32_t t0, t1, t2, t3;
                ldm_x4(t0, t1, t2, t3, sb + R_BHI + rowB[nt] + kbyt);
                bh[2*nt][0] = t0; bh[2*nt][1] = t2;
                bh[2*nt+1][0] = t1; bh[2*nt+1][1] = t3;
                ldm_x4(t0, t1, t2, t3, sb + R_BLO + rowB[nt] + kbyt);
                bl[2*nt][0] = t0; bl[2*nt][1] = t2;
                bl[2*nt+1][0] = t1; bl[2*nt+1][1] = t3;
            }
#pragma unroll
            for (int mt = 0; mt < 2; mt++)
#pragma unroll
                for (int j = 0; j < 8; j++) {
                    mma16816(acc[mt][j], ah[mt], bh[j]);
                    mma16816(acc[mt][j], ah[mt], bl[j]);
                    mma16816(acc[mt][j], al[mt], bh[j]);
                }
        }
        __syncthreads();
    }

    const int gid = lane >> 2;
    const int tig = lane & 3;
#pragma unroll
    for (int mt = 0; mt < 2; mt++) {
#pragma unroll
        for (int j = 0; j < 8; j++) {
            const int col = bn + wn * 64 + j * 8 + tig * 2;
            if (col < ncols) {
                const float bx = bias[col], by = bias[col + 1];
                const size_t r0 = (size_t)(bm + wm * 32 + mt * 16 + gid);
                const size_t r1 = r0 + 8;
                float2 v0 = make_float2(acc[mt][j][0] + bx, acc[mt][j][1] + by);
                float2 v1 = make_float2(acc[mt][j][2] + bx, acc[mt][j][3] + by);
                *(float2*)(C + r0 * (size_t)ldc + col) = v0;
                *(float2*)(C + r1 * (size_t)ldc + col) = v1;
            }
        }
    }
}

/* ------------------------------------------------------------------ */
/* Recurrent step on mma.sync bf16 3-pass:                             */
/*   h' = tanh(A[64,2048] @ W[2048,2048]^T + X)                        */
/* grid (32 n-strips, 8 k-slices), 256 thr, 64x64x256 per block,       */
/* BK=64 double-buffered cp.async, 144B padded rows (conflict-free).   */
/* Last block per strip reduces 8 partials + X, tanh, writes bf16      */
/* hi/lo (feeds next step and the later big GEMMs).                    */
/* ------------------------------------------------------------------ */
#define SROWB  144
#define R2_AH  0
#define R2_AL  9216
#define R2_BH  18432
#define R2_BL  27648
#define STAGE2 36864
#define STEP_SMEM (2 * STAGE2)

__global__ __launch_bounds__(256, 1) void rnn_step_mma(
    const __nv_bfloat16* __restrict__ Ahi, const __nv_bfloat16* __restrict__ Alo,
    const __nv_bfloat16* __restrict__ Whi, const __nv_bfloat16* __restrict__ Wlo,
    const float* __restrict__ Xadd, float* __restrict__ part,
    __nv_bfloat162* __restrict__ outHi, __nv_bfloat162* __restrict__ outLo)
{
    extern __shared__ char smem[];
    __shared__ int s_last;
    const uint32_t smbase = s2u(smem);

    const int tid  = threadIdx.x;
    const int lane = tid & 31;
    const int wid  = tid >> 5;
    const int wm   = wid & 3;          /* m-group: 16 rows      */
    const int wn   = wid >> 2;         /* n-group: 32 cols      */
    const int strip  = blockIdx.x;     /* 0..31 (64 cols each)  */
    const int kslice = blockIdx.y;     /* 0..7  (256 k each)    */
    const int kbase0 = kslice * 256;

    /* loaders: 4 threads per row, 2x16B chunks each, 4 arrays */
    const int lrow = tid >> 2;
    const int c0   = (tid & 3) * 2;
    const uint32_t dOff = (uint32_t)(lrow * SROWB + c0 * 16);
    const size_t aO = (size_t)lrow * 2048 + (size_t)c0 * 8;
    const size_t bO = (size_t)(strip * 64 + lrow) * 2048 + (size_t)c0 * 8;

    auto issue = [&](int it) {
        const uint32_t sb = smbase + (uint32_t)(it & 1) * STAGE2;
        const size_t kb = (size_t)(kbase0 + it * 64);
        cpa16(sb + R2_AH + dOff,      Ahi + aO + kb,     16);
        cpa16(sb + R2_AH + dOff + 16, Ahi + aO + kb + 8, 16);
        cpa16(sb + R2_AL + dOff,      Alo + aO + kb,     16);
        cpa16(sb + R2_AL + dOff + 16, Alo + aO + kb + 8, 16);
        cpa16(sb + R2_BH + dOff,      Whi + bO + kb,     16);
        cpa16(sb + R2_BH + dOff + 16, Whi + bO + kb + 8, 16);
        cpa16(sb + R2_BL + dOff,      Wlo + bO + kb,     16);
        cpa16(sb + R2_BL + dOff + 16, Wlo + bO + kb + 8, 16);
        cpa_commit();
    };

    const int rlane = lane & 15;
    const int khalf = (lane >> 4) * 16;
    const uint32_t arow = (uint32_t)((wm * 16 + rlane) * SROWB);
    uint32_t brow[2];
    brow[0] = (uint32_t)((wn * 32 + rlane) * SROWB);
    brow[1] = (uint32_t)((wn * 32 + 16 + rlane) * SROWB);

    float acc[4][4];
#pragma unroll
    for (int j = 0; j < 4; j++)
#pragma unroll
        for (int q = 0; q < 4; q++) acc[j][q] = 0.f;

    issue(0);

    for (int it = 0; it < 4; it++) {
        if (it < 3) {
            issue(it + 1);
            asm volatile("cp.async.wait_group 1;" ::: "memory");
        } else {
            asm volatile("cp.async.wait_group 0;" ::: "memory");
        }
        __syncthreads();

        const uint32_t sb = smbase + (uint32_t)(it & 1) * STAGE2;
#pragma unroll
        for (int kk = 0; kk < 4; kk++) {
            const uint32_t kbyt = (uint32_t)(kk * 32 + khalf);
            uint32_t ah[4], al[4];
            ldm_x4(ah[0], ah[1], ah[2], ah[3], sb + R2_AH + arow + kbyt);
            ldm_x4(al[0], al[1], al[2], al[3], sb + R2_AL + arow + kbyt);
            uint32_t bh[4][2], bl[4][2];
#pragma unroll
            for (int nt = 0; nt < 2; nt++) {
                uint32_t t0, t1, t2, t3;
                ldm_x4(t0, t1, t2, t3, sb + R2_BH + brow[nt] + kbyt);
                bh[2*nt][0] = t0; bh[2*nt][1] = t2;
                bh[2*nt+1][0] = t1; bh[2*nt+1][1] = t3;
                ldm_x4(t0, t1, t2, t3, sb + R2_BL + brow[nt] + kbyt);
                bl[2*nt][0] = t0; bl[2*nt][1] = t2;
                bl[2*nt+1][0] = t1; bl[2*nt+1][1] = t3;
            }
#pragma unroll
            for (int j = 0; j < 4; j++) {
                mma16816(acc[j], ah, bh[j]);
                mma16816(acc[j], ah, bl[j]);
                mma16816(acc[j], al, bh[j]);
            }
        }
        __syncthreads();
    }

    /* partial write */
    float* dst = part + (size_t)kslice * BH;
    const int r0 = wm * 16 + (lane >> 2);
#pragma unroll
    for (int j = 0; j < 4; j++) {
        const int col = strip * 64 + wn * 32 + j * 8 + (lane & 3) * 2;
        *(float2*)(dst + (size_t)r0 * 2048 + col) =
            make_float2(acc[j][0], acc[j][1]);
        *(float2*)(dst + (size_t)(r0 + 8) * 2048 + col) =
            make_float2(acc[j][2], acc[j][3]);
    }

    /* last-block finalize for this strip */
    __threadfence();
    if (tid == 0) {
        int old = atomicAdd(&g_cnt[strip], 1);
        s_last = (old == 7) ? 1 : 0;
    }
    __syncthreads();
    if (!s_last) return;
    __threadfence();

    const float4* p4 = (const float4*)part;
    const float4* x4 = (const float4*)Xadd;
    for (int u = tid; u < 1024; u += 256) {      /* 64 rows x 16 float4 */
        const int m  = u >> 4;
        const int c4 = u & 15;
        const size_t off = (size_t)m * 512 + (size_t)strip * 16 + c4;
        float4 sv = p4[off];
#pragma unroll
        for (int kg = 1; kg < 8; kg++) {
            float4 p = p4[(size_t)kg * (BH / 4) + off];
            sv.x += p.x; sv.y += p.y; sv.z += p.z; sv.w += p.w;
        }
        float4 xv = x4[off];
        sv.x = tanhf(sv.x + xv.x); sv.y = tanhf(sv.y + xv.y);
        sv.z = tanhf(sv.z + xv.z); sv.w = tanhf(sv.w + xv.w);

        __nv_bfloat16 hx = __float2bfloat16(sv.x), hy = __float2bfloat16(sv.y);
        __nv_bfloat16 hz = __float2bfloat16(sv.z), hw = __float2bfloat16(sv.w);
        __nv_bfloat162 a; a.x = hx; a.y = hy;
        __nv_bfloat162 b; b.x = hz; b.y = hw;
        outHi[2 * off] = a; outHi[2 * off + 1] = b;
        __nv_bfloat162 la, lb;
        la.x = __float2bfloat16(sv.x - __bfloat162float(hx));
        la.y = __float2bfloat16(sv.y - __bfloat162float(hy));
        lb.x = __float2bfloat16(sv.z - __bfloat162float(hz));
        lb.y = __float2bfloat16(sv.w - __bfloat162float(hw));
        outLo[2 * off] = la; outLo[2 * off + 1] = lb;
    }
    __threadfence();
    __syncthreads();
    if (tid == 0) g_cnt[strip] = 0;
}

/* ------------------------------------------------------------------ */
/* final hidden: reconstruct fp32 = hi + lo                            */
/* ------------------------------------------------------------------ */
__global__ void copy_final_hl(
    const __nv_bfloat162* __restrict__ h0h, const __nv_bfloat162* __restrict__ h0l,
    const __nv_bfloat162* __restrict__ h1h, const __nv_bfloat162* __restrict__ h1l,
    float2* __restrict__ out)
{
    const int i = blockIdx.x * 256 + threadIdx.x;    /* 0 .. BH-1 pairs */
    if (i >= BH) return;
    const __nv_bfloat162 h = (i < BH / 2) ? h0h[i] : h1h[i - BH / 2];
    const __nv_bfloat162 l = (i < BH / 2) ? h0l[i] : h1l[i - BH / 2];
    float2 v;
    v.x = __bfloat162float(h.x) + __bfloat162float(l.x);
    v.y = __bfloat162float(h.y) + __bfloat162float(l.y);
    out[i] = v;
}

/* ------------------------------------------------------------------ */
extern "C" void kernel_launch(void* const* d_in, const int* in_sizes, int n_in,
                              void* d_out, int out_size)
{
    (void)in_sizes; (void)n_in; (void)out_size;

    const void*  inputs = d_in[0];
    const float* hidden = (const float*)d_in[1];
    const float* emb    = (const float*)d_in[2];
    const float* W0     = (const float*)d_in[3];
    const float* b0     = (const float*)d_in[4];
    const float* W1     = (const float*)d_in[5];
    const float* b1     = (const float*)d_in[6];
    const float* Wout   = (const float*)d_in[7];
    const float* bout   = (const float*)d_in[8];
    float* out = (float*)d_out;

    float *pX0, *pX1, *pPart;
    __nv_bfloat16 *pEh, *pEl, *pW0xh, *pW0xl, *pW0hh, *pW0hl;
    __nv_bfloat16 *pW1xh, *pW1xl, *pW1hh, *pW1hl, *pWoh, *pWol;
    __nv_bfloat16 *pH0h, *pH0l, *pH1h, *pH1l, *pHIh, *pHIl;
    cudaGetSymbolAddress((void**)&pX0,   g_X0);
    cudaGetSymbolAddress((void**)&pX1,   g_X1);
    cudaGetSymbolAddress((void**)&pPart, g_part);
    cudaGetSymbolAddress((void**)&pEh,   g_emb_hi);
    cudaGetSymbolAddress((void**)&pEl,   g_emb_lo);
    cudaGetSymbolAddress((void**)&pW0xh, g_w0x_hi);
    cudaGetSymbolAddress((void**)&pW0xl, g_w0x_lo);
    cudaGetSymbolAddress((void**)&pW0hh, g_w0h_hi);
    cudaGetSymbolAddress((void**)&pW0hl, g_w0h_lo);
    cudaGetSymbolAddress((void**)&pW1xh, g_w1x_hi);
    cudaGetSymbolAddress((void**)&pW1xl, g_w1x_lo);
    cudaGetSymbolAddress((void**)&pW1hh, g_w1h_hi);
    cudaGetSymbolAddress((void**)&pW1hl, g_w1h_lo);
    cudaGetSymbolAddress((void**)&pWoh,  g_wout_hi);
    cudaGetSymbolAddress((void**)&pWol,  g_wout_lo);
    cudaGetSymbolAddress((void**)&pH0h,  g_H0_hi);
    cudaGetSymbolAddress((void**)&pH0l,  g_H0_lo);
    cudaGetSymbolAddress((void**)&pH1h,  g_H1_hi);
    cudaGetSymbolAddress((void**)&pH1l,  g_H1_lo);
    cudaGetSymbolAddress((void**)&pHIh,  g_hin_hi);
    cudaGetSymbolAddress((void**)&pHIl,  g_hin_lo);

    static int smem_set = 0;
    if (!smem_set) {
        cudaFuncSetAttribute(gemm_mma, cudaFuncAttributeMaxDynamicSharedMemorySize,
                             GEMM_SMEM);
        cudaFuncSetAttribute(rnn_step_mma, cudaFuncAttributeMaxDynamicSharedMemorySize,
                             STEP_SMEM);
        smem_set = 1;
    }

    detect_idx_kernel<<<1, 32>>>((const unsigned int*)inputs);

    /* hi/lo conversions (weights, embedding, initial hidden) */
    {
        long n4;
        n4 = (long)VOCAB * (EMB / 4);
        conv_split<<<(unsigned)((n4 + 255) / 256), 256>>>(
            (const float4*)emb, n4, 9, 9, (__nv_bfloat162*)pEh, (__nv_bfloat162*)pEl);
        n4 = (long)VOCAB * (HID / 4);
        conv_split<<<(unsigned)((n4 + 255) / 256), 256>>>(
            (const float4*)Wout, n4, 9, 9, (__nv_bfloat162*)pWoh, (__nv_bfloat162*)pWol);
        n4 = (long)HID * (HID / 4);
        conv_split<<<(unsigned)((n4 + 255) / 256), 256>>>(
            (const float4*)W0, n4, 9, 10,
            (__nv_bfloat162*)pW0xh, (__nv_bfloat162*)pW0xl);
        conv_split<<<(unsigned)((n4 + 255) / 256), 256>>>(
            (const float4*)(W0 + 2048), n4, 9, 10,
            (__nv_bfloat162*)pW0hh, (__nv_bfloat162*)pW0hl);
        conv_split<<<(unsigned)((n4 + 255) / 256), 256>>>(
            (const float4*)W1, n4, 9, 10,
            (__nv_bfloat162*)pW1xh, (__nv_bfloat162*)pW1xl);
        conv_split<<<(unsigned)((n4 + 255) / 256), 256>>>(
            (const float4*)(W1 + 2048), n4, 9, 10,
            (__nv_bfloat162*)pW1hh, (__nv_bfloat162*)pW1hl);
        n4 = (long)(2 * BH) / 4;
        conv_split<<<(unsigned)((n4 + 255) / 256), 256>>>(
            (const float4*)hidden, n4, 9, 9,
            (__nv_bfloat162*)pHIh, (__nv_bfloat162*)pHIl);
    }

    /* X0 = emb[inputs] @ W0x^T + b0 */
    {
        dim3 g(HID / 128, MB_ / 128);
        gemm_mma<<<g, 256, GEMM_SMEM>>>(pEh, pEl, inputs,
                                        pW0xh, pW0xl, HID, b0, pX0, HID, HID);
    }

    const dim3 gs(32, 8);

    /* layer-0 recurrence: h0(t) = tanh(X0[t] + h0(t-1) @ W0h^T) */
    for (int t = 0; t < T_SEQ; t++) {
        const __nv_bfloat16* ah = t ? (pH0h + (size_t)(t - 1) * BH) : pHIh;
        const __nv_bfloat16* al = t ? (pH0l + (size_t)(t - 1) * BH) : pHIl;
        rnn_step_mma<<<gs, 256, STEP_SMEM>>>(
            ah, al, pW0hh, pW0hl, pX0 + (size_t)t * BH, pPart,
            (__nv_bfloat162*)(pH0h + (size_t)t * BH),
            (__nv_bfloat162*)(pH0l + (size_t)t * BH));
    }

    /* X1 = H0 @ W1x^T + b1  (parallel big GEMM) */
    {
        dim3 g(HID / 128, MB_ / 128);
        gemm_mma<<<g, 256, GEMM_SMEM>>>(pH0h, pH0l, (const void*)0,
                                        pW1xh, pW1xl, HID, b1, pX1, HID, HID);
    }

    /* layer-1 recurrence: h1(t) = tanh(X1[t] + h1(t-1) @ W1h^T) */
    for (int t = 0; t < T_SEQ; t++) {
        const __nv_bfloat16* ah = t ? (pH1h + (size_t)(t - 1) * BH) : (pHIh + BH);
        const __nv_bfloat16* al = t ? (pH1l + (size_t)(t - 1) * BH) : (pHIl + BH);
        rnn_step_mma<<<gs, 256, STEP_SMEM>>>(
            ah, al, pW1hh, pW1hl, pX1 + (size_t)t * BH, pPart,
            (__nv_bfloat162*)(pH1h + (size_t)t * BH),
            (__nv_bfloat162*)(pH1l + (size_t)t * BH));
    }

    /* logits = H1 @ Wout^T + bout */
    {
        dim3 g((VOCAB + 127) / 128, MB_ / 128);
        gemm_mma<<<g, 256, GEMM_SMEM>>>(pH1h, pH1l, (const void*)0,
                                        pWoh, pWol, VOCAB, bout, out, VOCAB, VOCAB);
    }

    /* final hidden = hi + lo of last step, both layers */
    copy_final_hl<<<(BH + 255) / 256, 256>>>(
        (const __nv_bfloat162*)(pH0h + (size_t)(T_SEQ - 1) * BH),
        (const __nv_bfloat162*)(pH0l + (size_t)(T_SEQ - 1) * BH),
        (const __nv_bfloat162*)(pH1h + (size_t)(T_SEQ - 1) * BH),
        (const __nv_bfloat162*)(pH1l + (size_t)(T_SEQ - 1) * BH),
        (float2*)(out + (size_t)MB_ * VOCAB));
}

// round 9
// speedup vs baseline: 4.4927x; 1.0241x over previous
#include <cuda_runtime.h>
#include <cuda_bf16.h>
#include <math.h>
#include <stdint.h>

#define T_SEQ 128
#define BATCH 64
#define EMB   2048
#define HID   2048
#define VOCAB 10000
#define MB_   (T_SEQ * BATCH)   /* 8192 */
#define BH    (BATCH * HID)     /* 131072 */

/* ------------------------------------------------------------------ */
/* Scratch (device globals only)                                       */
/* ------------------------------------------------------------------ */
__device__ float g_X0[(size_t)MB_ * HID];
__device__ float g_X1[(size_t)MB_ * HID];
__device__ float g_part[8][BH];
__device__ int   g_cnt[32];
__device__ int   g_is64;

__device__ __nv_bfloat16 g_emb_hi [(size_t)VOCAB * EMB];
__device__ __nv_bfloat16 g_emb_lo [(size_t)VOCAB * EMB];
__device__ __nv_bfloat16 g_w0x_hi [(size_t)HID * HID];
__device__ __nv_bfloat16 g_w0x_lo [(size_t)HID * HID];
__device__ __nv_bfloat16 g_w0h_hi [(size_t)HID * HID];
__device__ __nv_bfloat16 g_w0h_lo [(size_t)HID * HID];
__device__ __nv_bfloat16 g_w1x_hi [(size_t)HID * HID];
__device__ __nv_bfloat16 g_w1x_lo [(size_t)HID * HID];
__device__ __nv_bfloat16 g_w1h_hi [(size_t)HID * HID];
__device__ __nv_bfloat16 g_w1h_lo [(size_t)HID * HID];
__device__ __nv_bfloat16 g_wout_hi[(size_t)VOCAB * HID];
__device__ __nv_bfloat16 g_wout_lo[(size_t)VOCAB * HID];
__device__ __nv_bfloat16 g_H0_hi  [(size_t)MB_ * HID];
__device__ __nv_bfloat16 g_H0_lo  [(size_t)MB_ * HID];
__device__ __nv_bfloat16 g_H1_hi  [(size_t)MB_ * HID];
__device__ __nv_bfloat16 g_H1_lo  [(size_t)MB_ * HID];
__device__ __nv_bfloat16 g_hin_hi [2 * BH];
__device__ __nv_bfloat16 g_hin_lo [2 * BH];

/* ------------------------------------------------------------------ */
__device__ __forceinline__ uint32_t s2u(const void* p) {
    uint32_t a;
    asm("{ .reg .u64 t; cvta.to.shared.u64 t, %1; cvt.u32.u64 %0, t; }"
        : "=r"(a) : "l"(p));
    return a;
}
__device__ __forceinline__ void ldm_x4(uint32_t& r0, uint32_t& r1,
                                       uint32_t& r2, uint32_t& r3, uint32_t a) {
    asm volatile("ldmatrix.sync.aligned.m8n8.x4.shared.b16 {%0,%1,%2,%3}, [%4];"
                 : "=r"(r0), "=r"(r1), "=r"(r2), "=r"(r3) : "r"(a));
}
__device__ __forceinline__ void mma16816(float* c, const uint32_t* a,
                                         const uint32_t* b) {
    asm volatile(
        "mma.sync.aligned.m16n8k16.row.col.f32.bf16.bf16.f32 "
        "{%0,%1,%2,%3}, {%4,%5,%6,%7}, {%8,%9}, {%0,%1,%2,%3};"
        : "+f"(c[0]), "+f"(c[1]), "+f"(c[2]), "+f"(c[3])
        : "r"(a[0]), "r"(a[1]), "r"(a[2]), "r"(a[3]), "r"(b[0]), "r"(b[1]));
}
__device__ __forceinline__ void cpa16(uint32_t dst, const void* src, int srcsz) {
    asm volatile("cp.async.cg.shared.global [%0], [%1], 16, %2;"
                 :: "r"(dst), "l"(src), "r"(srcsz) : "memory");
}
__device__ __forceinline__ void cpa_commit() {
    asm volatile("cp.async.commit_group;" ::: "memory");
}

/* ------------------------------------------------------------------ */
__global__ void detect_idx_kernel(const unsigned int* __restrict__ p) {
    if (threadIdx.x == 0) {
        unsigned int o = 0;
#pragma unroll
        for (int i = 0; i < 16; i++) o |= p[2 * i + 1];
        g_is64 = (o == 0u) ? 1 : 0;
    }
}

/* ------------------------------------------------------------------ */
/* fp32 -> bf16 hi/lo split                                            */
/* ------------------------------------------------------------------ */
__global__ void conv_split(const float4* __restrict__ src, long n4,
                           int c4s, int ld4s,
                           __nv_bfloat162* __restrict__ hi,
                           __nv_bfloat162* __restrict__ lo)
{
    long i = (long)blockIdx.x * 256 + threadIdx.x;
    if (i >= n4) return;
    long r = i >> c4s;
    long c = i & ((1L << c4s) - 1);
    float4 v = src[(r << ld4s) + c];
    __nv_bfloat16 hx = __float2bfloat16(v.x), hy = __float2bfloat16(v.y);
    __nv_bfloat16 hz = __float2bfloat16(v.z), hw = __float2bfloat16(v.w);
    __nv_bfloat162 h0; h0.x = hx; h0.y = hy;
    __nv_bfloat162 h1; h1.x = hz; h1.y = hw;
    hi[2 * i] = h0; hi[2 * i + 1] = h1;
    __nv_bfloat162 l0, l1;
    l0.x = __float2bfloat16(v.x - __bfloat162float(hx));
    l0.y = __float2bfloat16(v.y - __bfloat162float(hy));
    l1.x = __float2bfloat16(v.z - __bfloat162float(hz));
    l1.y = __float2bfloat16(v.w - __bfloat162float(hw));
    lo[2 * i] = l0; lo[2 * i + 1] = l1;
}

/* ------------------------------------------------------------------ */
/* Big mma.sync bf16 3-pass GEMM, 4-stage cp.async pipeline:           */
/*   C[M,N] = A[M,K=2048] * B[N,K]^T + bias                            */
/* ------------------------------------------------------------------ */
#define ROWB   80
#define R_AHI  0
#define R_ALO  10240
#define R_BHI  20480
#define R_BLO  30720
#define STAGEB 40960
#define NSTG   4
#define GEMM_SMEM (NSTG * STAGEB)   /* 160 KB */

__global__ __launch_bounds__(256, 1) void gemm_mma(
    const __nv_bfloat16* __restrict__ Ahi, const __nv_bfloat16* __restrict__ Alo,
    const void* __restrict__ aidx,
    const __nv_bfloat16* __restrict__ Bhi, const __nv_bfloat16* __restrict__ Blo,
    int nrowsB, const float* __restrict__ bias,
    float* __restrict__ C, int ldc, int ncols)
{
    extern __shared__ char smem[];
    const uint32_t smbase = s2u(smem);

    const int tid  = threadIdx.x;
    const int lane = tid & 31;
    const int wid  = tid >> 5;
    const int wm   = wid & 3;
    const int wn   = wid >> 2;
    const int bm   = blockIdx.y * 128;
    const int bn   = blockIdx.x * 128;

    const int lrow  = tid >> 1;
    const int cpair = (tid & 1) * 2;
    const uint32_t dstOff = (uint32_t)(lrow * ROWB + cpair * 16);

    size_t aoff;
    {
        const int m = bm + lrow;
        size_t row;
        if (aidx) {
            if (g_is64) row = (size_t)((const long long*)aidx)[m];
            else        row = (size_t)((const int*)aidx)[m];
        } else row = (size_t)m;
        aoff = row * 2048 + (size_t)cpair * 8;
    }
    const int  nrow = bn + lrow;
    const int  bsz  = (nrow < nrowsB) ? 16 : 0;
    const size_t boff = (size_t)((nrow < nrowsB) ? nrow : 0) * 2048
                      + (size_t)cpair * 8;

    const int rlane  = lane & 15;
    const int khalf2 = (lane >> 4) * 16;
    uint32_t rowA[2], rowB[4];
#pragma unroll
    for (int mt = 0; mt < 2; mt++)
        rowA[mt] = (uint32_t)((wm * 32 + mt * 16 + rlane) * ROWB);
#pragma unroll
    for (int nt = 0; nt < 4; nt++)
        rowB[nt] = (uint32_t)((wn * 64 + nt * 16 + rlane) * ROWB);

    float acc[2][8][4];
#pragma unroll
    for (int mt = 0; mt < 2; mt++)
#pragma unroll
        for (int j = 0; j < 8; j++)
#pragma unroll
            for (int q = 0; q < 4; q++) acc[mt][j][q] = 0.f;

    const int NIT = 2048 / 32;   /* 64 */

    auto issue = [&](int it) {
        const uint32_t sb = smbase + (uint32_t)(it & (NSTG - 1)) * STAGEB;
        const size_t kb = (size_t)it * 32;
        cpa16(sb + R_AHI + dstOff,      Ahi + aoff + kb,     16);
        cpa16(sb + R_AHI + dstOff + 16, Ahi + aoff + kb + 8, 16);
        cpa16(sb + R_ALO + dstOff,      Alo + aoff + kb,     16);
        cpa16(sb + R_ALO + dstOff + 16, Alo + aoff + kb + 8, 16);
        cpa16(sb + R_BHI + dstOff,      Bhi + boff + kb,     bsz);
        cpa16(sb + R_BHI + dstOff + 16, Bhi + boff + kb + 8, bsz);
        cpa16(sb + R_BLO + dstOff,      Blo + boff + kb,     bsz);
        cpa16(sb + R_BLO + dstOff + 16, Blo + boff + kb + 8, bsz);
        cpa_commit();
    };

    issue(0); issue(1); issue(2);

    for (int it = 0; it < NIT; it++) {
        asm volatile("cp.async.wait_group 2;" ::: "memory");
        __syncthreads();
        /* fill the buffer computed last iteration ( (it+3)%4 == (it-1)%4 ) */
        if (it + NSTG - 1 < NIT) issue(it + NSTG - 1);
        else                     cpa_commit();

        const uint32_t sb = smbase + (uint32_t)(it & (NSTG - 1)) * STAGEB;
#pragma unroll
        for (int kk = 0; kk < 2; kk++) {
            const uint32_t kbyt = (uint32_t)(kk * 32 + khalf2);
            uint32_t ah[2][4], al[2][4];
#pragma unroll
            for (int mt = 0; mt < 2; mt++) {
                ldm_x4(ah[mt][0], ah[mt][1], ah[mt][2], ah[mt][3],
                       sb + R_AHI + rowA[mt] + kbyt);
                ldm_x4(al[mt][0], al[mt][1], al[mt][2], al[mt][3],
                       sb + R_ALO + rowA[mt] + kbyt);
            }
            uint32_t bh[8][2], bl[8][2];
#pragma unroll
            for (int nt = 0; nt < 4; nt++) {
                uint32_t t0, t1, t2, t3;
                ldm_x4(t0, t1, t2, t3, sb + R_BHI + rowB[nt] + kbyt);
                bh[2*nt][0] = t0; bh[2*nt][1] = t2;
                bh[2*nt+1][0] = t1; bh[2*nt+1][1] = t3;
                ldm_x4(t0, t1, t2, t3, sb + R_BLO + rowB[nt] + kbyt);
                bl[2*nt][0] = t0; bl[2*nt][1] = t2;
                bl[2*nt+1][0] = t1; bl[2*nt+1][1] = t3;
            }
#pragma unroll
            for (int mt = 0; mt < 2; mt++)
#pragma unroll
                for (int j = 0; j < 8; j++) {
                    mma16816(acc[mt][j], ah[mt], bh[j]);
                    mma16816(acc[mt][j], ah[mt], bl[j]);
                    mma16816(acc[mt][j], al[mt], bh[j]);
                }
        }
    }

    const int gid = lane >> 2;
    const int tig = lane & 3;
#pragma unroll
    for (int mt = 0; mt < 2; mt++) {
#pragma unroll
        for (int j = 0; j < 8; j++) {
            const int col = bn + wn * 64 + j * 8 + tig * 2;
            if (col < ncols) {
                const float bx = bias[col], by = bias[col + 1];
                const size_t r0 = (size_t)(bm + wm * 32 + mt * 16 + gid);
                const size_t r1 = r0 + 8;
                float2 v0 = make_float2(acc[mt][j][0] + bx, acc[mt][j][1] + by);
                float2 v1 = make_float2(acc[mt][j][2] + bx, acc[mt][j][3] + by);
                *(float2*)(C + r0 * (size_t)ldc + col) = v0;
                *(float2*)(C + r1 * (size_t)ldc + col) = v1;
            }
        }
    }
}

/* ------------------------------------------------------------------ */
/* Recurrent step on mma.sync bf16 3-pass, 3-stage pipeline:           */
/*   h' = tanh(A[64,2048] @ W[2048,2048]^T + X)                        */
/* grid (32 strips, 8 k-slices), 64x64x256/block, BK=64.               */
/* 3 stages x 36KB = 108KB -> still 2 CTAs/SM.                         */
/* ------------------------------------------------------------------ */
#define SROWB  144
#define R2_AH  0
#define R2_AL  9216
#define R2_BH  18432
#define R2_BL  27648
#define STAGE2 36864
#define STEP_SMEM (3 * STAGE2)   /* 108 KB */

__global__ __launch_bounds__(256, 1) void rnn_step_mma(
    const __nv_bfloat16* __restrict__ Ahi, const __nv_bfloat16* __restrict__ Alo,
    const __nv_bfloat16* __restrict__ Whi, const __nv_bfloat16* __restrict__ Wlo,
    const float* __restrict__ Xadd, float* __restrict__ part,
    __nv_bfloat162* __restrict__ outHi, __nv_bfloat162* __restrict__ outLo)
{
    extern __shared__ char smem[];
    __shared__ int s_last;
    const uint32_t smbase = s2u(smem);

    const int tid  = threadIdx.x;
    const int lane = tid & 31;
    const int wid  = tid >> 5;
    const int wm   = wid & 3;
    const int wn   = wid >> 2;
    const int strip  = blockIdx.x;
    const int kslice = blockIdx.y;
    const int kbase0 = kslice * 256;

    const int lrow = tid >> 2;
    const int c0   = (tid & 3) * 2;
    const uint32_t dOff = (uint32_t)(lrow * SROWB + c0 * 16);
    const size_t aO = (size_t)lrow * 2048 + (size_t)c0 * 8;
    const size_t bO = (size_t)(strip * 64 + lrow) * 2048 + (size_t)c0 * 8;

    auto issue = [&](int it) {
        const uint32_t sb = smbase + (uint32_t)(it % 3) * STAGE2;
        const size_t kb = (size_t)(kbase0 + it * 64);
        cpa16(sb + R2_AH + dOff,      Ahi + aO + kb,     16);
        cpa16(sb + R2_AH + dOff + 16, Ahi + aO + kb + 8, 16);
        cpa16(sb + R2_AL + dOff,      Alo + aO + kb,     16);
        cpa16(sb + R2_AL + dOff + 16, Alo + aO + kb + 8, 16);
        cpa16(sb + R2_BH + dOff,      Whi + bO + kb,     16);
        cpa16(sb + R2_BH + dOff + 16, Whi + bO + kb + 8, 16);
        cpa16(sb + R2_BL + dOff,      Wlo + bO + kb,     16);
        cpa16(sb + R2_BL + dOff + 16, Wlo + bO + kb + 8, 16);
        cpa_commit();
    };

    const int rlane = lane & 15;
    const int khalf = (lane >> 4) * 16;
    const uint32_t arow = (uint32_t)((wm * 16 + rlane) * SROWB);
    uint32_t brow[2];
    brow[0] = (uint32_t)((wn * 32 + rlane) * SROWB);
    brow[1] = (uint32_t)((wn * 32 + 16 + rlane) * SROWB);

    float acc[4][4];
#pragma unroll
    for (int j = 0; j < 4; j++)
#pragma unroll
        for (int q = 0; q < 4; q++) acc[j][q] = 0.f;

    issue(0); issue(1);

    for (int it = 0; it < 4; it++) {
        asm volatile("cp.async.wait_group 1;" ::: "memory");
        __syncthreads();
        if (it + 2 < 4) issue(it + 2);
        else            cpa_commit();

        const uint32_t sb = smbase + (uint32_t)(it % 3) * STAGE2;
#pragma unroll
        for (int kk = 0; kk < 4; kk++) {
            const uint32_t kbyt = (uint32_t)(kk * 32 + khalf);
            uint32_t ah[4], al[4];
            ldm_x4(ah[0], ah[1], ah[2], ah[3], sb + R2_AH + arow + kbyt);
            ldm_x4(al[0], al[1], al[2], al[3], sb + R2_AL + arow + kbyt);
            uint32_t bh[4][2], bl[4][2];
#pragma unroll
            for (int nt = 0; nt < 2; nt++) {
                uint32_t t0, t1, t2, t3;
                ldm_x4(t0, t1, t2, t3, sb + R2_BH + brow[nt] + kbyt);
                bh[2*nt][0] = t0; bh[2*nt][1] = t2;
                bh[2*nt+1][0] = t1; bh[2*nt+1][1] = t3;
                ldm_x4(t0, t1, t2, t3, sb + R2_BL + brow[nt] + kbyt);
                bl[2*nt][0] = t0; bl[2*nt][1] = t2;
                bl[2*nt+1][0] = t1; bl[2*nt+1][1] = t3;
            }
#pragma unroll
            for (int j = 0; j < 4; j++) {
                mma16816(acc[j], ah, bh[j]);
                mma16816(acc[j], ah, bl[j]);
                mma16816(acc[j], al, bh[j]);
            }
        }
    }

    /* partial write */
    float* dst = part + (size_t)kslice * BH;
    const int r0 = wm * 16 + (lane >> 2);
#pragma unroll
    for (int j = 0; j < 4; j++) {
        const int col = strip * 64 + wn * 32 + j * 8 + (lane & 3) * 2;
        *(float2*)(dst + (size_t)r0 * 2048 + col) =
            make_float2(acc[j][0], acc[j][1]);
        *(float2*)(dst + (size_t)(r0 + 8) * 2048 + col) =
            make_float2(acc[j][2], acc[j][3]);
    }

    /* last-block finalize for this strip */
    __threadfence();
    if (tid == 0) {
        int old = atomicAdd(&g_cnt[strip], 1);
        s_last = (old == 7) ? 1 : 0;
    }
    __syncthreads();
    if (!s_last) return;
    __threadfence();

    const float4* p4 = (const float4*)part;
    const float4* x4 = (const float4*)Xadd;
    for (int u = tid; u < 1024; u += 256) {
        const int m  = u >> 4;
        const int c4 = u & 15;
        const size_t off = (size_t)m * 512 + (size_t)strip * 16 + c4;
        float4 sv = p4[off];
#pragma unroll
        for (int kg = 1; kg < 8; kg++) {
            float4 p = p4[(size_t)kg * (BH / 4) + off];
            sv.x += p.x; sv.y += p.y; sv.z += p.z; sv.w += p.w;
        }
        float4 xv = x4[off];
        sv.x = tanhf(sv.x + xv.x); sv.y = tanhf(sv.y + xv.y);
        sv.z = tanhf(sv.z + xv.z); sv.w = tanhf(sv.w + xv.w);

        __nv_bfloat16 hx = __float2bfloat16(sv.x), hy = __float2bfloat16(sv.y);
        __nv_bfloat16 hz = __float2bfloat16(sv.z), hw = __float2bfloat16(sv.w);
        __nv_bfloat162 a; a.x = hx; a.y = hy;
        __nv_bfloat162 b; b.x = hz; b.y = hw;
        outHi[2 * off] = a; outHi[2 * off + 1] = b;
        __nv_bfloat162 la, lb;
        la.x = __float2bfloat16(sv.x - __bfloat162float(hx));
        la.y = __float2bfloat16(sv.y - __bfloat162float(hy));
        lb.x = __float2bfloat16(sv.z - __bfloat162float(hz));
        lb.y = __float2bfloat16(sv.w - __bfloat162float(hw));
        outLo[2 * off] = la; outLo[2 * off + 1] = lb;
    }
    __threadfence();
    __syncthreads();
    if (tid == 0) g_cnt[strip] = 0;
}

/* ------------------------------------------------------------------ */
__global__ void copy_final_hl(
    const __nv_bfloat162* __restrict__ h0h, const __nv_bfloat162* __restrict__ h0l,
    const __nv_bfloat162* __restrict__ h1h, const __nv_bfloat162* __restrict__ h1l,
    float2* __restrict__ out)
{
    const int i = blockIdx.x * 256 + threadIdx.x;
    if (i >= BH) return;
    const __nv_bfloat162 h = (i < BH / 2) ? h0h[i] : h1h[i - BH / 2];
    const __nv_bfloat162 l = (i < BH / 2) ? h0l[i] : h1l[i - BH / 2];
    float2 v;
    v.x = __bfloat162float(h.x) + __bfloat162float(l.x);
    v.y = __bfloat162float(h.y) + __bfloat162float(l.y);
    out[i] = v;
}

/* ------------------------------------------------------------------ */
extern "C" void kernel_launch(void* const* d_in, const int* in_sizes, int n_in,
                              void* d_out, int out_size)
{
    (void)in_sizes; (void)n_in; (void)out_size;

    const void*  inputs = d_in[0];
    const float* hidden = (const float*)d_in[1];
    const float* emb    = (const float*)d_in[2];
    const float* W0     = (const float*)d_in[3];
    const float* b0     = (const float*)d_in[4];
    const float* W1     = (const float*)d_in[5];
    const float* b1     = (const float*)d_in[6];
    const float* Wout   = (const float*)d_in[7];
    const float* bout   = (const float*)d_in[8];
    float* out = (float*)d_out;

    float *pX0, *pX1, *pPart;
    __nv_bfloat16 *pEh, *pEl, *pW0xh, *pW0xl, *pW0hh, *pW0hl;
    __nv_bfloat16 *pW1xh, *pW1xl, *pW1hh, *pW1hl, *pWoh, *pWol;
    __nv_bfloat16 *pH0h, *pH0l, *pH1h, *pH1l, *pHIh, *pHIl;
    cudaGetSymbolAddress((void**)&pX0,   g_X0);
    cudaGetSymbolAddress((void**)&pX1,   g_X1);
    cudaGetSymbolAddress((void**)&pPart, g_part);
    cudaGetSymbolAddress((void**)&pEh,   g_emb_hi);
    cudaGetSymbolAddress((void**)&pEl,   g_emb_lo);
    cudaGetSymbolAddress((void**)&pW0xh, g_w0x_hi);
    cudaGetSymbolAddress((void**)&pW0xl, g_w0x_lo);
    cudaGetSymbolAddress((void**)&pW0hh, g_w0h_hi);
    cudaGetSymbolAddress((void**)&pW0hl, g_w0h_lo);
    cudaGetSymbolAddress((void**)&pW1xh, g_w1x_hi);
    cudaGetSymbolAddress((void**)&pW1xl, g_w1x_lo);
    cudaGetSymbolAddress((void**)&pW1hh, g_w1h_hi);
    cudaGetSymbolAddress((void**)&pW1hl, g_w1h_lo);
    cudaGetSymbolAddress((void**)&pWoh,  g_wout_hi);
    cudaGetSymbolAddress((void**)&pWol,  g_wout_lo);
    cudaGetSymbolAddress((void**)&pH0h,  g_H0_hi);
    cudaGetSymbolAddress((void**)&pH0l,  g_H0_lo);
    cudaGetSymbolAddress((void**)&pH1h,  g_H1_hi);
    cudaGetSymbolAddress((void**)&pH1l,  g_H1_lo);
    cudaGetSymbolAddress((void**)&pHIh,  g_hin_hi);
    cudaGetSymbolAddress((void**)&pHIl,  g_hin_lo);

    static int smem_set = 0;
    if (!smem_set) {
        cudaFuncSetAttribute(gemm_mma, cudaFuncAttributeMaxDynamicSharedMemorySize,
                             GEMM_SMEM);
        cudaFuncSetAttribute(rnn_step_mma, cudaFuncAttributeMaxDynamicSharedMemorySize,
                             STEP_SMEM);
        smem_set = 1;
    }

    detect_idx_kernel<<<1, 32>>>((const unsigned int*)inputs);

    /* hi/lo conversions */
    {
        long n4;
        n4 = (long)VOCAB * (EMB / 4);
        conv_split<<<(unsigned)((n4 + 255) / 256), 256>>>(
            (const float4*)emb, n4, 9, 9, (__nv_bfloat162*)pEh, (__nv_bfloat162*)pEl);
        n4 = (long)VOCAB * (HID / 4);
        conv_split<<<(unsigned)((n4 + 255) / 256), 256>>>(
            (const float4*)Wout, n4, 9, 9, (__nv_bfloat162*)pWoh, (__nv_bfloat162*)pWol);
        n4 = (long)HID * (HID / 4);
        conv_split<<<(unsigned)((n4 + 255) / 256), 256>>>(
            (const float4*)W0, n4, 9, 10,
            (__nv_bfloat162*)pW0xh, (__nv_bfloat162*)pW0xl);
        conv_split<<<(unsigned)((n4 + 255) / 256), 256>>>(
            (const float4*)(W0 + 2048), n4, 9, 10,
            (__nv_bfloat162*)pW0hh, (__nv_bfloat162*)pW0hl);
        conv_split<<<(unsigned)((n4 + 255) / 256), 256>>>(
            (const float4*)W1, n4, 9, 10,
            (__nv_bfloat162*)pW1xh, (__nv_bfloat162*)pW1xl);
        conv_split<<<(unsigned)((n4 + 255) / 256), 256>>>(
            (const float4*)(W1 + 2048), n4, 9, 10,
            (__nv_bfloat162*)pW1hh, (__nv_bfloat162*)pW1hl);
        n4 = (long)(2 * BH) / 4;
        conv_split<<<(unsigned)((n4 + 255) / 256), 256>>>(
            (const float4*)hidden, n4, 9, 9,
            (__nv_bfloat162*)pHIh, (__nv_bfloat162*)pHIl);
    }

    /* X0 = emb[inputs] @ W0x^T + b0 */
    {
        dim3 g(HID / 128, MB_ / 128);
        gemm_mma<<<g, 256, GEMM_SMEM>>>(pEh, pEl, inputs,
                                        pW0xh, pW0xl, HID, b0, pX0, HID, HID);
    }

    const dim3 gs(32, 8);

    /* layer-0 recurrence */
    for (int t = 0; t < T_SEQ; t++) {
        const __nv_bfloat16* ah = t ? (pH0h + (size_t)(t - 1) * BH) : pHIh;
        const __nv_bfloat16* al = t ? (pH0l + (size_t)(t - 1) * BH) : pHIl;
        rnn_step_mma<<<gs, 256, STEP_SMEM>>>(
            ah, al, pW0hh, pW0hl, pX0 + (size_t)t * BH, pPart,
            (__nv_bfloat162*)(pH0h + (size_t)t * BH),
            (__nv_bfloat162*)(pH0l + (size_t)t * BH));
    }

    /* X1 = H0 @ W1x^T + b1 */
    {
        dim3 g(HID / 128, MB_ / 128);
        gemm_mma<<<g, 256, GEMM_SMEM>>>(pH0h, pH0l, (const void*)0,
                                        pW1xh, pW1xl, HID, b1, pX1, HID, HID);
    }

    /* layer-1 recurrence */
    for (int t = 0; t < T_SEQ; t++) {
        const __nv_bfloat16* ah = t ? (pH1h + (size_t)(t - 1) * BH) : (pHIh + BH);
        const __nv_bfloat16* al = t ? (pH1l + (size_t)(t - 1) * BH) : (pHIl + BH);
        rnn_step_mma<<<gs, 256, STEP_SMEM>>>(
            ah, al, pW1hh, pW1hl, pX1 + (size_t)t * BH, pPart,
            (__nv_bfloat162*)(pH1h + (size_t)t * BH),
            (__nv_bfloat162*)(pH1l + (size_t)t * BH));
    }

    /* logits = H1 @ Wout^T + bout */
    {
        dim3 g((VOCAB + 127) / 128, MB_ / 128);
        gemm_mma<<<g, 256, GEMM_SMEM>>>(pH1h, pH1l, (const void*)0,
                                        pWoh, pWol, VOCAB, bout, out, VOCAB, VOCAB);
    }

    copy_final_hl<<<(BH + 255) / 256, 256>>>(
        (const __nv_bfloat162*)(pH0h + (size_t)(T_SEQ - 1) * BH),
        (const __nv_bfloat162*)(pH0l + (size_t)(T_SEQ - 1) * BH),
        (const __nv_bfloat162*)(pH1h + (size_t)(T_SEQ - 1) * BH),
        (const __nv_bfloat162*)(pH1l + (size_t)(T_SEQ - 1) * BH),
        (float2*)(out + (size_t)MB_ * VOCAB));
}